// round 14
// baseline (speedup 1.0000x reference)
#include <cuda_runtime.h>
#include <cuda_fp16.h>
#include <math.h>

// Problem constants
#define BB   2
#define SS_  4096
#define DD   512
#define HH   8
#define DEP  64
#define BH   16
#define MM   8192

// fp16 copies of inputs/weights
__device__ __half g_xq[MM * DD];
__device__ __half g_xk[MM * DD];
__device__ __half g_xv[MM * DD];
__device__ __half g_wq[DD * DD];
__device__ __half g_wk[DD * DD];
__device__ __half g_wv[DD * DD];
__device__ __half g_wo[DD * DD];
// Q/K/V head-split [bh][s][d] fp16; ctx fp16 row-major.
__device__ __half g_qh[BH * SS_ * DEP];
__device__ __half g_kh[BH * SS_ * DEP];
__device__ __half g_vh[BH * SS_ * DEP];
__device__ __half g_ctxh[MM * DD];
__device__ float  g_inv[BH * SS_];

__device__ __forceinline__ float ex2(float x) {
    float y;
    asm("ex2.approx.ftz.f32 %0, %1;" : "=f"(y) : "f"(x));
    return y;
}

__device__ __forceinline__ void mma_f16(float* d, const unsigned* a, const unsigned* b) {
    asm volatile(
        "mma.sync.aligned.m16n8k16.row.col.f32.f16.f16.f32 "
        "{%0,%1,%2,%3}, {%4,%5,%6,%7}, {%8,%9}, {%0,%1,%2,%3};"
        : "+f"(d[0]), "+f"(d[1]), "+f"(d[2]), "+f"(d[3])
        : "r"(a[0]), "r"(a[1]), "r"(a[2]), "r"(a[3]), "r"(b[0]), "r"(b[1]));
}

__device__ __forceinline__ void ldsm4(unsigned* r, unsigned a) {
    asm volatile("ldmatrix.sync.aligned.m8n8.x4.shared.b16 {%0,%1,%2,%3}, [%4];"
                 : "=r"(r[0]), "=r"(r[1]), "=r"(r[2]), "=r"(r[3]) : "r"(a));
}
__device__ __forceinline__ void ldsm4t(unsigned* r, unsigned a) {
    asm volatile("ldmatrix.sync.aligned.m8n8.x4.trans.shared.b16 {%0,%1,%2,%3}, [%4];"
                 : "=r"(r[0]), "=r"(r[1]), "=r"(r[2]), "=r"(r[3]) : "r"(a));
}

__device__ __forceinline__ void cp16(void* smem_ptr, const void* gptr) {
    unsigned s = (unsigned)__cvta_generic_to_shared(smem_ptr);
    asm volatile("cp.async.cg.shared.global [%0], [%1], 16;" :: "r"(s), "l"(gptr));
}
#define CP_COMMIT() asm volatile("cp.async.commit_group;" ::: "memory")
#define CP_WAIT0()  asm volatile("cp.async.wait_group 0;" ::: "memory")
#define CP_WAIT1()  asm volatile("cp.async.wait_group 1;" ::: "memory")

// ---------------------------------------------------------------------------
__global__ void __launch_bounds__(256)
f32to16(const float* __restrict__ src, __half* __restrict__ dst) {
    const int i = blockIdx.x * 256 + threadIdx.x;   // float4 index
    float4 v = __ldcs(&((const float4*)src)[i]);
    __half2 a = __floats2half2_rn(v.x, v.y);
    __half2 b = __floats2half2_rn(v.z, v.w);
    uint2 u;
    u.x = *(unsigned*)&a; u.y = *(unsigned*)&b;
    *(uint2*)&dst[(size_t)i * 4] = u;
}

// ---------------------------------------------------------------------------
// Zero-fill attn upper triangle: block rt zeroes cols >= 128*(rt+1) for its
// 128 rows. Depends on nothing -> runs concurrently with projections/rowsum.
// ---------------------------------------------------------------------------
__global__ void __launch_bounds__(256)
zerofill_attn(float* __restrict__ attn) {
    const int rt = 31 - blockIdx.x;
    const int bh = blockIdx.y;
    const int row0 = rt * 128;
    const int w = threadIdx.x >> 5, lane = threadIdx.x & 31;
    const int c0 = (rt + 1) * 128;
    const float4 z4 = make_float4(0.f, 0.f, 0.f, 0.f);
#pragma unroll 1
    for (int rr = 0; rr < 16; rr++) {
        float* rowp = attn + ((size_t)bh * SS_ + row0 + w * 16 + rr) * SS_;
        for (int c = c0 + lane * 4; c < SS_; c += 128)
            __stcs((float4*)(rowp + c), z4);
    }
}

// ---------------------------------------------------------------------------
// fp16 GEMM: Y(8192x512) = Xh @ Wh + bias.  m16n8k16, ldmatrix, cp.async x2.
// MODE 0: fp32 row-major out. MODE 1: head-split [bh][s][d] fp16 out.
// ---------------------------------------------------------------------------
template <int MODE>
__global__ void __launch_bounds__(256, 2)
gemm_f16k(const __half* __restrict__ X, const __half* __restrict__ W,
          const float* __restrict__ bias, float* __restrict__ Y) {
    extern __shared__ __half hsm[];
    __half* Xb[2] = {hsm, hsm + 5120};              // [m][k] stride 40
    __half* Wb[2] = {hsm + 10240, hsm + 14592};     // [k][n] stride 136

    const int tid = threadIdx.x;
    const int lane = tid & 31, w = tid >> 5;
    const int g = lane >> 2, t = lane & 3;
    const int wm = w & 3, wn = w >> 2;
    const int m0 = blockIdx.y * 128, n0 = blockIdx.x * 128;

    const unsigned sbase = (unsigned)__cvta_generic_to_shared(hsm);
    const unsigned offA = ((lane & 15) * 40 + (lane >> 4) * 8) * 2;
    const unsigned offB = ((lane & 15) * 136 + (lane >> 4) * 8) * 2;

    float acc[2][8][4];
#pragma unroll
    for (int mt = 0; mt < 2; mt++)
#pragma unroll
        for (int nt = 0; nt < 8; nt++)
#pragma unroll
            for (int c = 0; c < 4; c++) acc[mt][nt][c] = 0.f;

    const int xr = tid >> 1;
    const int xc = (tid & 1) * 16;
    const int wr = tid >> 3;
    const int wc = (tid & 7) * 16;

#pragma unroll
    for (int i = 0; i < 2; i++) {
        cp16(&Xb[0][xr * 40 + xc + i * 8], &X[(size_t)(m0 + xr) * 512 + xc + i * 8]);
        cp16(&Wb[0][wr * 136 + wc + i * 8], &W[(size_t)wr * 512 + n0 + wc + i * 8]);
    }
    CP_COMMIT();
    CP_WAIT0();
    __syncthreads();

    for (int it = 0; it < 16; it++) {
        if (it < 15) {
            const int k0 = (it + 1) * 32;
            __half* Xn = Xb[(it + 1) & 1];
            __half* Wn = Wb[(it + 1) & 1];
#pragma unroll
            for (int i = 0; i < 2; i++) {
                cp16(&Xn[xr * 40 + xc + i * 8], &X[(size_t)(m0 + xr) * 512 + k0 + xc + i * 8]);
                cp16(&Wn[wr * 136 + wc + i * 8], &W[(size_t)(k0 + wr) * 512 + n0 + wc + i * 8]);
            }
            CP_COMMIT();
        }
        const unsigned Xp = sbase + (it & 1) * 5120 * 2;
        const unsigned Wp = sbase + 10240 * 2 + (it & 1) * 4352 * 2;

#pragma unroll
        for (int ks = 0; ks < 2; ks++) {
            unsigned a[2][4];
#pragma unroll
            for (int mt = 0; mt < 2; mt++)
                ldsm4(a[mt], Xp + ((wm * 32 + mt * 16) * 40 + ks * 16) * 2 + offA);
#pragma unroll
            for (int ntp = 0; ntp < 4; ntp++) {
                unsigned bv[4];
                ldsm4t(bv, Wp + (ks * 16 * 136 + wn * 64 + ntp * 16) * 2 + offB);
#pragma unroll
                for (int mt = 0; mt < 2; mt++) {
                    mma_f16(acc[mt][2 * ntp],     a[mt], bv);
                    mma_f16(acc[mt][2 * ntp + 1], a[mt], bv + 2);
                }
            }
        }
        if (it < 15) {
            CP_WAIT0();
            __syncthreads();
        }
    }

    __half* Yh = (__half*)Y;
#pragma unroll
    for (int nt = 0; nt < 8; nt++) {
        const int colg = n0 + wn * 64 + nt * 8 + 2 * t;
        const float b0 = bias[colg], b1 = bias[colg + 1];
#pragma unroll
        for (int mt = 0; mt < 2; mt++) {
            const int rbase = m0 + wm * 32 + mt * 16;
#pragma unroll
            for (int half_ = 0; half_ < 2; half_++) {
                const int r = rbase + g + half_ * 8;
                float ox = acc[mt][nt][half_ * 2 + 0] + b0;
                float oy = acc[mt][nt][half_ * 2 + 1] + b1;
                if (MODE == 0) {
                    *(float2*)&Y[(size_t)r * 512 + colg] = make_float2(ox, oy);
                } else {
                    const int b = r >> 12, s = r & 4095;
                    const int h = colg >> 6, din = colg & 63;
                    *(__half2*)&Yh[(((size_t)(b * 8 + h)) * SS_ + s) * DEP + din] =
                        __floats2half2_rn(ox, oy);
                }
            }
        }
    }
}

// ---------------------------------------------------------------------------
// Rowsum prepass: GEMM1 replay (Q K^T, exp, causal) -> g_inv.
// ---------------------------------------------------------------------------
__global__ void __launch_bounds__(256)
rowsum_kernel() {
    extern __shared__ __half smh[];
    __half* Qs = smh;

    const int tid = threadIdx.x;
    const int lane = tid & 31, w = tid >> 5;
    const int g = lane >> 2, t = lane & 3;
    const int rt = 31 - blockIdx.x;
    const int bh = blockIdx.y;
    const int row0 = rt * 128;

    const __half* __restrict__ Qh = g_qh + (size_t)bh * SS_ * DEP;
    const __half* __restrict__ Kh = g_kh + (size_t)bh * SS_ * DEP;

    const unsigned sbase = (unsigned)__cvta_generic_to_shared(smh);
    const unsigned kbase = sbase + 9216 * 2;

    const unsigned offA = (((lane & 15) * 72 + (lane >> 4) * 8) * 2);
    const unsigned offK = ((((lane >> 4) * 8 + (lane & 7)) * 72 + ((lane >> 3) & 1) * 8) * 2);
    const unsigned qpA = sbase + (w * 16 * 72) * 2 + offA;

    const int kvr = tid >> 2;
    const int c4 = tid & 3;

    {
        const int qr = tid >> 1;
        const int qo = (tid & 1) * 32;
#pragma unroll
        for (int i = 0; i < 4; i++)
            cp16(&Qs[qr * 72 + qo + i * 8], &Qh[(size_t)(row0 + qr) * DEP + qo + i * 8]);
    }
    __half* K0 = smh + 9216;
#pragma unroll
    for (int i = 0; i < 2; i++) {
        const int ho = 8 * c4 + 32 * i;
        cp16(&K0[kvr * 72 + ho], &Kh[(size_t)kvr * DEP + ho]);
    }
    CP_COMMIT();
    {
        __half* K1 = smh + 9216 + 4608;
#pragma unroll
        for (int i = 0; i < 2; i++) {
            const int ho = 8 * c4 + 32 * i;
            cp16(&K1[kvr * 72 + ho], &Kh[(size_t)(64 + kvr) * DEP + ho]);
        }
        CP_COMMIT();
    }
    CP_WAIT1();
    __syncthreads();

    unsigned qa[4][4];
#pragma unroll
    for (int ks = 0; ks < 4; ks++) ldsm4(qa[ks], qpA + ks * 32);

    float rs0 = 0.f, rs1 = 0.f;
    const int gi0 = row0 + w * 16 + g;
    const int gi1 = gi0 + 8;
    const int ctmax = 2 * rt + 1;
    const float C = 0.18033688f;  // 0.125 * log2(e)

    for (int ct = 0; ct <= ctmax; ct++) {
        if (ct + 2 <= ctmax) {
            const int st = (ct + 2) % 3;
            __half* Kn = smh + 9216 + st * 4608;
            const size_t gr = (size_t)((ct + 2) * 64 + kvr) * DEP;
#pragma unroll
            for (int i = 0; i < 2; i++) {
                const int ho = 8 * c4 + 32 * i;
                cp16(&Kn[kvr * 72 + ho], &Kh[gr + ho]);
            }
            CP_COMMIT();
        }

        const unsigned Kbp = kbase + (ct % 3) * 4608 * 2;

        float s[8][4];
#pragma unroll
        for (int nt = 0; nt < 8; nt++)
#pragma unroll
            for (int c = 0; c < 4; c++) s[nt][c] = 0.f;
#pragma unroll
        for (int ks = 0; ks < 4; ks++) {
#pragma unroll
            for (int ntp = 0; ntp < 4; ntp++) {
                unsigned bk[4];
                ldsm4(bk, Kbp + ntp * 2304 + ks * 32 + offK);
                mma_f16(s[2 * ntp],     qa[ks], bk);
                mma_f16(s[2 * ntp + 1], qa[ks], bk + 2);
            }
        }

#pragma unroll
        for (int nt = 0; nt < 8; nt++) {
            const int cj = ct * 64 + nt * 8 + 2 * t;
            rs0 += (cj     <= gi0) ? ex2(s[nt][0] * C) : 0.f;
            rs0 += (cj + 1 <= gi0) ? ex2(s[nt][1] * C) : 0.f;
            rs1 += (cj     <= gi1) ? ex2(s[nt][2] * C) : 0.f;
            rs1 += (cj + 1 <= gi1) ? ex2(s[nt][3] * C) : 0.f;
        }

        if (ct < ctmax) {
            if (ct + 2 <= ctmax) { CP_WAIT1(); } else { CP_WAIT0(); }
            __syncthreads();
        }
    }

    rs0 += __shfl_xor_sync(0xffffffffu, rs0, 1);
    rs0 += __shfl_xor_sync(0xffffffffu, rs0, 2);
    rs1 += __shfl_xor_sync(0xffffffffu, rs1, 1);
    rs1 += __shfl_xor_sync(0xffffffffu, rs1, 2);
    if (t == 0) {
        g_inv[(size_t)bh * SS_ + gi0] = 1.f / rs0;
        g_inv[(size_t)bh * SS_ + gi1] = 1.f / rs1;
    }
}

// ---------------------------------------------------------------------------
// Causal flash attention. Writes NORMALIZED P (lower triangle + masked zeros
// inside its tiles) and fp16 ctx. Upper triangle handled by zerofill_attn.
// ---------------------------------------------------------------------------
__global__ void __launch_bounds__(256, 2)
attn_kernel(float* __restrict__ attn_out, int write_attn) {
    extern __shared__ __half smh[];
    __half* Qs = smh;

    const int tid = threadIdx.x;
    const int lane = tid & 31, w = tid >> 5;
    const int g = lane >> 2, t = lane & 3;
    const int rt = 31 - blockIdx.x;
    const int bh = blockIdx.y;
    const int row0 = rt * 128;

    const __half* __restrict__ Qh = g_qh + (size_t)bh * SS_ * DEP;
    const __half* __restrict__ Kh = g_kh + (size_t)bh * SS_ * DEP;
    const __half* __restrict__ Vh = g_vh + (size_t)bh * SS_ * DEP;

    const unsigned sbase = (unsigned)__cvta_generic_to_shared(smh);
    const unsigned kbase = sbase + 9216 * 2;
    const unsigned vbase = sbase + 23040 * 2;

    const unsigned offA = (((lane & 15) * 72 + (lane >> 4) * 8) * 2);
    const unsigned offK = ((((lane >> 4) * 8 + (lane & 7)) * 72 + ((lane >> 3) & 1) * 8) * 2);
    const unsigned qpA = sbase + (w * 16 * 72) * 2 + offA;

    const int kvr = tid >> 2;
    const int c4 = tid & 3;

    const int gi0 = row0 + w * 16 + g;
    const int gi1 = gi0 + 8;

    const float inv0 = g_inv[(size_t)bh * SS_ + gi0];
    const float inv1 = g_inv[(size_t)bh * SS_ + gi1];

    {
        const int qr = tid >> 1;
        const int qo = (tid & 1) * 32;
#pragma unroll
        for (int i = 0; i < 4; i++)
            cp16(&Qs[qr * 72 + qo + i * 8], &Qh[(size_t)(row0 + qr) * DEP + qo + i * 8]);
    }
    __half* K0 = smh + 9216;
    __half* V0 = smh + 23040;
#pragma unroll
    for (int i = 0; i < 2; i++) {
        const int ho = 8 * c4 + 32 * i;
        cp16(&K0[kvr * 72 + ho], &Kh[(size_t)kvr * DEP + ho]);
        cp16(&V0[kvr * 72 + ho], &Vh[(size_t)kvr * DEP + ho]);
    }
    CP_COMMIT();
    {
        __half* K1 = smh + 9216 + 4608;
        __half* V1 = smh + 23040 + 4608;
#pragma unroll
        for (int i = 0; i < 2; i++) {
            const int ho = 8 * c4 + 32 * i;
            cp16(&K1[kvr * 72 + ho], &Kh[(size_t)(64 + kvr) * DEP + ho]);
            cp16(&V1[kvr * 72 + ho], &Vh[(size_t)(64 + kvr) * DEP + ho]);
        }
        CP_COMMIT();
    }
    CP_WAIT1();
    __syncthreads();

    unsigned qa[4][4];
#pragma unroll
    for (int ks = 0; ks < 4; ks++) ldsm4(qa[ks], qpA + ks * 32);

    float ctx[8][4];
#pragma unroll
    for (int nt = 0; nt < 8; nt++)
#pragma unroll
        for (int c = 0; c < 4; c++) ctx[nt][c] = 0.f;

    const int ctmax = 2 * rt + 1;
    const float C = 0.18033688f;

    for (int ct = 0; ct <= ctmax; ct++) {
        if (ct + 2 <= ctmax) {
            const int st = (ct + 2) % 3;
            __half* Kn = smh + 9216 + st * 4608;
            __half* Vn = smh + 23040 + st * 4608;
            const size_t gr = (size_t)((ct + 2) * 64 + kvr) * DEP;
#pragma unroll
            for (int i = 0; i < 2; i++) {
                const int ho = 8 * c4 + 32 * i;
                cp16(&Kn[kvr * 72 + ho], &Kh[gr + ho]);
                cp16(&Vn[kvr * 72 + ho], &Vh[gr + ho]);
            }
            CP_COMMIT();
        }

        const int st = ct % 3;
        const unsigned Kbp = kbase + st * 4608 * 2;
        const unsigned Vbp = vbase + st * 4608 * 2;

        // GEMM1: S = Q K^T
        float s[8][4];
#pragma unroll
        for (int nt = 0; nt < 8; nt++)
#pragma unroll
            for (int c = 0; c < 4; c++) s[nt][c] = 0.f;
#pragma unroll
        for (int ks = 0; ks < 4; ks++) {
#pragma unroll
            for (int ntp = 0; ntp < 4; ntp++) {
                unsigned bk[4];
                ldsm4(bk, Kbp + ntp * 2304 + ks * 32 + offK);
                mma_f16(s[2 * ntp],     qa[ks], bk);
                mma_f16(s[2 * ntp + 1], qa[ks], bk + 2);
            }
        }

        // exp * inv (normalized); store fp32; stage fp16 (normalized)
#pragma unroll
        for (int nt = 0; nt < 8; nt++) {
            const int cj = ct * 64 + nt * 8 + 2 * t;
            float e00 = (cj     <= gi0) ? ex2(s[nt][0] * C) * inv0 : 0.f;
            float e01 = (cj + 1 <= gi0) ? ex2(s[nt][1] * C) * inv0 : 0.f;
            float e10 = (cj     <= gi1) ? ex2(s[nt][2] * C) * inv1 : 0.f;
            float e11 = (cj + 1 <= gi1) ? ex2(s[nt][3] * C) * inv1 : 0.f;
            if (write_attn) {
                __stcs((float2*)&attn_out[((size_t)bh * SS_ + gi0) * SS_ + cj],
                       make_float2(e00, e01));
                __stcs((float2*)&attn_out[((size_t)bh * SS_ + gi1) * SS_ + cj],
                       make_float2(e10, e11));
            }
            *(__half2*)&Qs[(w * 16 + g) * 72 + nt * 8 + 2 * t]     = __floats2half2_rn(e00, e01);
            *(__half2*)&Qs[(w * 16 + g + 8) * 72 + nt * 8 + 2 * t] = __floats2half2_rn(e10, e11);
        }
        __syncwarp();

        // GEMM2: ctx += P V
#pragma unroll
        for (int ks = 0; ks < 4; ks++) {
            unsigned pa[4];
            ldsm4(pa, qpA + ks * 32);
#pragma unroll
            for (int ntp = 0; ntp < 4; ntp++) {
                unsigned bv[4];
                ldsm4t(bv, Vbp + ks * 2304 + ntp * 32 + offA);
                mma_f16(ctx[2 * ntp],     pa, bv);
                mma_f16(ctx[2 * ntp + 1], pa, bv + 2);
            }
        }

        if (ct < ctmax) {
            if (ct + 2 <= ctmax) { CP_WAIT1(); } else { CP_WAIT0(); }
            __syncthreads();
        }
    }

    // Store ctx as fp16
    const int b = bh >> 3, h = bh & 7;
#pragma unroll
    for (int nt = 0; nt < 8; nt++) {
        const int d = nt * 8 + 2 * t;
        *(__half2*)&g_ctxh[((size_t)(b * SS_ + gi0)) * DD + h * 64 + d] =
            __floats2half2_rn(ctx[nt][0], ctx[nt][1]);
        *(__half2*)&g_ctxh[((size_t)(b * SS_ + gi1)) * DD + h * 64 + d] =
            __floats2half2_rn(ctx[nt][2], ctx[nt][3]);
    }
}

// ---------------------------------------------------------------------------
extern "C" void kernel_launch(void* const* d_in, const int* in_sizes, int n_in,
                              void* d_out, int out_size) {
    const float* q  = (const float*)d_in[2];
    const float* k  = (const float*)d_in[0];
    const float* v  = (const float*)d_in[1];
    const float* Wq = (const float*)d_in[4];
    const float* bq = (const float*)d_in[5];
    const float* Wk = (const float*)d_in[6];
    const float* bk = (const float*)d_in[7];
    const float* Wv = (const float*)d_in[8];
    const float* bv = (const float*)d_in[9];
    const float* Wo = (const float*)d_in[10];
    const float* bo = (const float*)d_in[11];

    float* out = (float*)d_out;
    const size_t BSD = (size_t)BB * SS_ * DD;
    const size_t ATT = (size_t)BH * SS_ * SS_;

    float* out_main = nullptr;
    float* attn_out = nullptr;
    if ((size_t)out_size >= BSD + ATT) {
        out_main = out;
        attn_out = out + BSD;
    } else if ((size_t)out_size >= ATT) {
        attn_out = out;
    } else {
        out_main = out;
    }

    void *pxq, *pxk, *pxv, *pwq, *pwk, *pwv, *pwo;
    void *pq, *pk, *pv, *pctx;
    cudaGetSymbolAddress(&pxq, g_xq);
    cudaGetSymbolAddress(&pxk, g_xk);
    cudaGetSymbolAddress(&pxv, g_xv);
    cudaGetSymbolAddress(&pwq, g_wq);
    cudaGetSymbolAddress(&pwk, g_wk);
    cudaGetSymbolAddress(&pwv, g_wv);
    cudaGetSymbolAddress(&pwo, g_wo);
    cudaGetSymbolAddress(&pq, g_qh);
    cudaGetSymbolAddress(&pk, g_kh);
    cudaGetSymbolAddress(&pv, g_vh);
    cudaGetSymbolAddress(&pctx, g_ctxh);

    cudaFuncSetAttribute(attn_kernel,
                         cudaFuncAttributeMaxDynamicSharedMemorySize, 73728);
    cudaFuncSetAttribute(rowsum_kernel,
                         cudaFuncAttributeMaxDynamicSharedMemorySize, 46080);
    cudaFuncSetAttribute(gemm_f16k<0>,
                         cudaFuncAttributeMaxDynamicSharedMemorySize, 37888);
    cudaFuncSetAttribute(gemm_f16k<1>,
                         cudaFuncAttributeMaxDynamicSharedMemorySize, 37888);

    // Side streams + fork/join events (capture-legal pattern; per-call cost
    // is capture-time only — replays are free).
    cudaStream_t sQ, sV, sZ;
    cudaStreamCreateWithFlags(&sQ, cudaStreamNonBlocking);
    cudaStreamCreateWithFlags(&sV, cudaStreamNonBlocking);
    cudaStreamCreateWithFlags(&sZ, cudaStreamNonBlocking);
    cudaEvent_t eRoot, eQ, eV, eZ;
    cudaEventCreateWithFlags(&eRoot, cudaEventDisableTiming);
    cudaEventCreateWithFlags(&eQ, cudaEventDisableTiming);
    cudaEventCreateWithFlags(&eV, cudaEventDisableTiming);
    cudaEventCreateWithFlags(&eZ, cudaEventDisableTiming);

    dim3 ggrid(4, 64);

    // Fork
    cudaEventRecord(eRoot, 0);
    cudaStreamWaitEvent(sQ, eRoot, 0);
    cudaStreamWaitEvent(sV, eRoot, 0);
    cudaStreamWaitEvent(sZ, eRoot, 0);

    // sQ: Q chain
    f32to16<<<4096, 256, 0, sQ>>>(q,  (__half*)pxq);
    f32to16<<<256,  256, 0, sQ>>>(Wq, (__half*)pwq);
    gemm_f16k<1><<<ggrid, 256, 37888, sQ>>>((const __half*)pxq, (const __half*)pwq, bq, (float*)pq);
    cudaEventRecord(eQ, sQ);

    // sV: V chain + Wo convert
    f32to16<<<4096, 256, 0, sV>>>(v,  (__half*)pxv);
    f32to16<<<256,  256, 0, sV>>>(Wv, (__half*)pwv);
    f32to16<<<256,  256, 0, sV>>>(Wo, (__half*)pwo);
    gemm_f16k<1><<<ggrid, 256, 37888, sV>>>((const __half*)pxv, (const __half*)pwv, bv, (float*)pv);
    cudaEventRecord(eV, sV);

    // sZ: upper-triangle zero-fill (no dependencies)
    if (attn_out) zerofill_attn<<<dim3(32, BH), 256, 0, sZ>>>(attn_out);
    cudaEventRecord(eZ, sZ);

    // main: K chain -> rowsum -> attn -> out-proj
    f32to16<<<4096, 256>>>(k,  (__half*)pxk);
    f32to16<<<256,  256>>>(Wk, (__half*)pwk);
    gemm_f16k<1><<<ggrid, 256, 37888>>>((const __half*)pxk, (const __half*)pwk, bk, (float*)pk);

    cudaStreamWaitEvent(0, eQ, 0);
    rowsum_kernel<<<dim3(32, BH), 256, 46080>>>();

    cudaStreamWaitEvent(0, eV, 0);
    cudaStreamWaitEvent(0, eZ, 0);
    attn_kernel<<<dim3(32, BH), 256, 73728>>>(attn_out, attn_out != nullptr);

    if (out_main) {
        gemm_f16k<0><<<ggrid, 256, 37888>>>((const __half*)pctx, (const __half*)pwo, bo, out_main);
    }

    cudaEventDestroy(eRoot);
    cudaEventDestroy(eQ);
    cudaEventDestroy(eV);
    cudaEventDestroy(eZ);
    cudaStreamDestroy(sQ);
    cudaStreamDestroy(sV);
    cudaStreamDestroy(sZ);
}

// round 15
// speedup vs baseline: 1.0885x; 1.0885x over previous
#include <cuda_runtime.h>
#include <cuda_fp16.h>
#include <math.h>

// Problem constants
#define BB   2
#define SS_  4096
#define DD   512
#define HH   8
#define DEP  64
#define BH   16
#define MM   8192

// fp16 copies of inputs/weights
__device__ __half g_xq[MM * DD];
__device__ __half g_xk[MM * DD];
__device__ __half g_xv[MM * DD];
__device__ __half g_wq[DD * DD];
__device__ __half g_wk[DD * DD];
__device__ __half g_wv[DD * DD];
__device__ __half g_wo[DD * DD];
// Q/K/V head-split [bh][s][d] fp16; ctx fp16 row-major.
__device__ __half g_qh[BH * SS_ * DEP];
__device__ __half g_kh[BH * SS_ * DEP];
__device__ __half g_vh[BH * SS_ * DEP];
__device__ __half g_ctxh[MM * DD];
__device__ float  g_inv[BH * SS_];

__device__ __forceinline__ float ex2(float x) {
    float y;
    asm("ex2.approx.ftz.f32 %0, %1;" : "=f"(y) : "f"(x));
    return y;
}

__device__ __forceinline__ void mma_f16(float* d, const unsigned* a, const unsigned* b) {
    asm volatile(
        "mma.sync.aligned.m16n8k16.row.col.f32.f16.f16.f32 "
        "{%0,%1,%2,%3}, {%4,%5,%6,%7}, {%8,%9}, {%0,%1,%2,%3};"
        : "+f"(d[0]), "+f"(d[1]), "+f"(d[2]), "+f"(d[3])
        : "r"(a[0]), "r"(a[1]), "r"(a[2]), "r"(a[3]), "r"(b[0]), "r"(b[1]));
}

__device__ __forceinline__ void ldsm4(unsigned* r, unsigned a) {
    asm volatile("ldmatrix.sync.aligned.m8n8.x4.shared.b16 {%0,%1,%2,%3}, [%4];"
                 : "=r"(r[0]), "=r"(r[1]), "=r"(r[2]), "=r"(r[3]) : "r"(a));
}
__device__ __forceinline__ void ldsm4t(unsigned* r, unsigned a) {
    asm volatile("ldmatrix.sync.aligned.m8n8.x4.trans.shared.b16 {%0,%1,%2,%3}, [%4];"
                 : "=r"(r[0]), "=r"(r[1]), "=r"(r[2]), "=r"(r[3]) : "r"(a));
}

__device__ __forceinline__ void cp16(void* smem_ptr, const void* gptr) {
    unsigned s = (unsigned)__cvta_generic_to_shared(smem_ptr);
    asm volatile("cp.async.cg.shared.global [%0], [%1], 16;" :: "r"(s), "l"(gptr));
}
#define CP_COMMIT() asm volatile("cp.async.commit_group;" ::: "memory")
#define CP_WAIT0()  asm volatile("cp.async.wait_group 0;" ::: "memory")
#define CP_WAIT1()  asm volatile("cp.async.wait_group 1;" ::: "memory")

// ---------------------------------------------------------------------------
__global__ void __launch_bounds__(256)
f32to16(const float* __restrict__ src, __half* __restrict__ dst) {
    const int i = blockIdx.x * 256 + threadIdx.x;   // float4 index
    float4 v = __ldcs(&((const float4*)src)[i]);
    __half2 a = __floats2half2_rn(v.x, v.y);
    __half2 b = __floats2half2_rn(v.z, v.w);
    uint2 u;
    u.x = *(unsigned*)&a; u.y = *(unsigned*)&b;
    *(uint2*)&dst[(size_t)i * 4] = u;
}

// ---------------------------------------------------------------------------
// fp16 GEMM: Y(8192x512) = Xh @ Wh + bias.  m16n8k16, ldmatrix, cp.async x2.
// MODE 0: fp32 row-major out. MODE 1: head-split [bh][s][d] fp16 out.
// ---------------------------------------------------------------------------
template <int MODE>
__global__ void __launch_bounds__(256, 2)
gemm_f16k(const __half* __restrict__ X, const __half* __restrict__ W,
          const float* __restrict__ bias, float* __restrict__ Y) {
    extern __shared__ __half hsm[];
    __half* Xb[2] = {hsm, hsm + 5120};              // [m][k] stride 40
    __half* Wb[2] = {hsm + 10240, hsm + 14592};     // [k][n] stride 136

    const int tid = threadIdx.x;
    const int lane = tid & 31, w = tid >> 5;
    const int g = lane >> 2, t = lane & 3;
    const int wm = w & 3, wn = w >> 2;
    const int m0 = blockIdx.y * 128, n0 = blockIdx.x * 128;

    const unsigned sbase = (unsigned)__cvta_generic_to_shared(hsm);
    const unsigned offA = ((lane & 15) * 40 + (lane >> 4) * 8) * 2;
    const unsigned offB = ((lane & 15) * 136 + (lane >> 4) * 8) * 2;

    float acc[2][8][4];
#pragma unroll
    for (int mt = 0; mt < 2; mt++)
#pragma unroll
        for (int nt = 0; nt < 8; nt++)
#pragma unroll
            for (int c = 0; c < 4; c++) acc[mt][nt][c] = 0.f;

    const int xr = tid >> 1;
    const int xc = (tid & 1) * 16;
    const int wr = tid >> 3;
    const int wc = (tid & 7) * 16;

#pragma unroll
    for (int i = 0; i < 2; i++) {
        cp16(&Xb[0][xr * 40 + xc + i * 8], &X[(size_t)(m0 + xr) * 512 + xc + i * 8]);
        cp16(&Wb[0][wr * 136 + wc + i * 8], &W[(size_t)wr * 512 + n0 + wc + i * 8]);
    }
    CP_COMMIT();
    CP_WAIT0();
    __syncthreads();

    for (int it = 0; it < 16; it++) {
        if (it < 15) {
            const int k0 = (it + 1) * 32;
            __half* Xn = Xb[(it + 1) & 1];
            __half* Wn = Wb[(it + 1) & 1];
#pragma unroll
            for (int i = 0; i < 2; i++) {
                cp16(&Xn[xr * 40 + xc + i * 8], &X[(size_t)(m0 + xr) * 512 + k0 + xc + i * 8]);
                cp16(&Wn[wr * 136 + wc + i * 8], &W[(size_t)(k0 + wr) * 512 + n0 + wc + i * 8]);
            }
            CP_COMMIT();
        }
        const unsigned Xp = sbase + (it & 1) * 5120 * 2;
        const unsigned Wp = sbase + 10240 * 2 + (it & 1) * 4352 * 2;

#pragma unroll
        for (int ks = 0; ks < 2; ks++) {
            unsigned a[2][4];
#pragma unroll
            for (int mt = 0; mt < 2; mt++)
                ldsm4(a[mt], Xp + ((wm * 32 + mt * 16) * 40 + ks * 16) * 2 + offA);
#pragma unroll
            for (int ntp = 0; ntp < 4; ntp++) {
                unsigned bv[4];
                ldsm4t(bv, Wp + (ks * 16 * 136 + wn * 64 + ntp * 16) * 2 + offB);
#pragma unroll
                for (int mt = 0; mt < 2; mt++) {
                    mma_f16(acc[mt][2 * ntp],     a[mt], bv);
                    mma_f16(acc[mt][2 * ntp + 1], a[mt], bv + 2);
                }
            }
        }
        if (it < 15) {
            CP_WAIT0();
            __syncthreads();
        }
    }

    __half* Yh = (__half*)Y;
#pragma unroll
    for (int nt = 0; nt < 8; nt++) {
        const int colg = n0 + wn * 64 + nt * 8 + 2 * t;
        const float b0 = bias[colg], b1 = bias[colg + 1];
#pragma unroll
        for (int mt = 0; mt < 2; mt++) {
            const int rbase = m0 + wm * 32 + mt * 16;
#pragma unroll
            for (int half_ = 0; half_ < 2; half_++) {
                const int r = rbase + g + half_ * 8;
                float ox = acc[mt][nt][half_ * 2 + 0] + b0;
                float oy = acc[mt][nt][half_ * 2 + 1] + b1;
                if (MODE == 0) {
                    *(float2*)&Y[(size_t)r * 512 + colg] = make_float2(ox, oy);
                } else {
                    const int b = r >> 12, s = r & 4095;
                    const int h = colg >> 6, din = colg & 63;
                    *(__half2*)&Yh[(((size_t)(b * 8 + h)) * SS_ + s) * DEP + din] =
                        __floats2half2_rn(ox, oy);
                }
            }
        }
    }
}

// ---------------------------------------------------------------------------
// Rowsum prepass: GEMM1 replay (Q K^T, exp, causal) -> g_inv.
// Epilogue: zero-fill attn upper triangle for this block's rows (rowsum's
// DRAM is ~2% busy — these 0.54 GB of stores ride along nearly free).
// ---------------------------------------------------------------------------
__global__ void __launch_bounds__(256)
rowsum_kernel(float* __restrict__ attn_out, int write_attn) {
    extern __shared__ __half smh[];
    __half* Qs = smh;

    const int tid = threadIdx.x;
    const int lane = tid & 31, w = tid >> 5;
    const int g = lane >> 2, t = lane & 3;
    const int rt = 31 - blockIdx.x;
    const int bh = blockIdx.y;
    const int row0 = rt * 128;

    const __half* __restrict__ Qh = g_qh + (size_t)bh * SS_ * DEP;
    const __half* __restrict__ Kh = g_kh + (size_t)bh * SS_ * DEP;

    const unsigned sbase = (unsigned)__cvta_generic_to_shared(smh);
    const unsigned kbase = sbase + 9216 * 2;

    const unsigned offA = (((lane & 15) * 72 + (lane >> 4) * 8) * 2);
    const unsigned offK = ((((lane >> 4) * 8 + (lane & 7)) * 72 + ((lane >> 3) & 1) * 8) * 2);
    const unsigned qpA = sbase + (w * 16 * 72) * 2 + offA;

    const int kvr = tid >> 2;
    const int c4 = tid & 3;

    {
        const int qr = tid >> 1;
        const int qo = (tid & 1) * 32;
#pragma unroll
        for (int i = 0; i < 4; i++)
            cp16(&Qs[qr * 72 + qo + i * 8], &Qh[(size_t)(row0 + qr) * DEP + qo + i * 8]);
    }
    __half* K0 = smh + 9216;
#pragma unroll
    for (int i = 0; i < 2; i++) {
        const int ho = 8 * c4 + 32 * i;
        cp16(&K0[kvr * 72 + ho], &Kh[(size_t)kvr * DEP + ho]);
    }
    CP_COMMIT();
    {
        __half* K1 = smh + 9216 + 4608;
#pragma unroll
        for (int i = 0; i < 2; i++) {
            const int ho = 8 * c4 + 32 * i;
            cp16(&K1[kvr * 72 + ho], &Kh[(size_t)(64 + kvr) * DEP + ho]);
        }
        CP_COMMIT();
    }
    CP_WAIT1();
    __syncthreads();

    unsigned qa[4][4];
#pragma unroll
    for (int ks = 0; ks < 4; ks++) ldsm4(qa[ks], qpA + ks * 32);

    float rs0 = 0.f, rs1 = 0.f;
    const int gi0 = row0 + w * 16 + g;
    const int gi1 = gi0 + 8;
    const int ctmax = 2 * rt + 1;
    const float C = 0.18033688f;  // 0.125 * log2(e)

    for (int ct = 0; ct <= ctmax; ct++) {
        if (ct + 2 <= ctmax) {
            const int st = (ct + 2) % 3;
            __half* Kn = smh + 9216 + st * 4608;
            const size_t gr = (size_t)((ct + 2) * 64 + kvr) * DEP;
#pragma unroll
            for (int i = 0; i < 2; i++) {
                const int ho = 8 * c4 + 32 * i;
                cp16(&Kn[kvr * 72 + ho], &Kh[gr + ho]);
            }
            CP_COMMIT();
        }

        const unsigned Kbp = kbase + (ct % 3) * 4608 * 2;

        float s[8][4];
#pragma unroll
        for (int nt = 0; nt < 8; nt++)
#pragma unroll
            for (int c = 0; c < 4; c++) s[nt][c] = 0.f;
#pragma unroll
        for (int ks = 0; ks < 4; ks++) {
#pragma unroll
            for (int ntp = 0; ntp < 4; ntp++) {
                unsigned bk[4];
                ldsm4(bk, Kbp + ntp * 2304 + ks * 32 + offK);
                mma_f16(s[2 * ntp],     qa[ks], bk);
                mma_f16(s[2 * ntp + 1], qa[ks], bk + 2);
            }
        }

#pragma unroll
        for (int nt = 0; nt < 8; nt++) {
            const int cj = ct * 64 + nt * 8 + 2 * t;
            rs0 += (cj     <= gi0) ? ex2(s[nt][0] * C) : 0.f;
            rs0 += (cj + 1 <= gi0) ? ex2(s[nt][1] * C) : 0.f;
            rs1 += (cj     <= gi1) ? ex2(s[nt][2] * C) : 0.f;
            rs1 += (cj + 1 <= gi1) ? ex2(s[nt][3] * C) : 0.f;
        }

        if (ct < ctmax) {
            if (ct + 2 <= ctmax) { CP_WAIT1(); } else { CP_WAIT0(); }
            __syncthreads();
        }
    }

    rs0 += __shfl_xor_sync(0xffffffffu, rs0, 1);
    rs0 += __shfl_xor_sync(0xffffffffu, rs0, 2);
    rs1 += __shfl_xor_sync(0xffffffffu, rs1, 1);
    rs1 += __shfl_xor_sync(0xffffffffu, rs1, 2);
    if (t == 0) {
        g_inv[(size_t)bh * SS_ + gi0] = 1.f / rs0;
        g_inv[(size_t)bh * SS_ + gi1] = 1.f / rs1;
    }

    // Epilogue: zero-fill upper triangle for this block's rows
    // (cols >= 128*(rt+1); disjoint from attn's lower-triangle writes).
    if (write_attn) {
        const int c0 = (rt + 1) * 128;
        const float4 z4 = make_float4(0.f, 0.f, 0.f, 0.f);
#pragma unroll 1
        for (int rr = 0; rr < 16; rr++) {
            float* rowp = attn_out + ((size_t)bh * SS_ + row0 + w * 16 + rr) * SS_;
            for (int c = c0 + lane * 4; c < SS_; c += 128)
                __stcs((float4*)(rowp + c), z4);
        }
    }
}

// ---------------------------------------------------------------------------
// Causal flash attention. Writes NORMALIZED P (lower triangle + masked zeros
// inside its tiles) and fp16 ctx. Upper triangle handled by rowsum epilogue.
// ---------------------------------------------------------------------------
__global__ void __launch_bounds__(256, 2)
attn_kernel(float* __restrict__ attn_out, int write_attn) {
    extern __shared__ __half smh[];
    __half* Qs = smh;

    const int tid = threadIdx.x;
    const int lane = tid & 31, w = tid >> 5;
    const int g = lane >> 2, t = lane & 3;
    const int rt = 31 - blockIdx.x;
    const int bh = blockIdx.y;
    const int row0 = rt * 128;

    const __half* __restrict__ Qh = g_qh + (size_t)bh * SS_ * DEP;
    const __half* __restrict__ Kh = g_kh + (size_t)bh * SS_ * DEP;
    const __half* __restrict__ Vh = g_vh + (size_t)bh * SS_ * DEP;

    const unsigned sbase = (unsigned)__cvta_generic_to_shared(smh);
    const unsigned kbase = sbase + 9216 * 2;
    const unsigned vbase = sbase + 23040 * 2;

    const unsigned offA = (((lane & 15) * 72 + (lane >> 4) * 8) * 2);
    const unsigned offK = ((((lane >> 4) * 8 + (lane & 7)) * 72 + ((lane >> 3) & 1) * 8) * 2);
    const unsigned qpA = sbase + (w * 16 * 72) * 2 + offA;

    const int kvr = tid >> 2;
    const int c4 = tid & 3;

    const int gi0 = row0 + w * 16 + g;
    const int gi1 = gi0 + 8;

    const float inv0 = g_inv[(size_t)bh * SS_ + gi0];
    const float inv1 = g_inv[(size_t)bh * SS_ + gi1];

    {
        const int qr = tid >> 1;
        const int qo = (tid & 1) * 32;
#pragma unroll
        for (int i = 0; i < 4; i++)
            cp16(&Qs[qr * 72 + qo + i * 8], &Qh[(size_t)(row0 + qr) * DEP + qo + i * 8]);
    }
    __half* K0 = smh + 9216;
    __half* V0 = smh + 23040;
#pragma unroll
    for (int i = 0; i < 2; i++) {
        const int ho = 8 * c4 + 32 * i;
        cp16(&K0[kvr * 72 + ho], &Kh[(size_t)kvr * DEP + ho]);
        cp16(&V0[kvr * 72 + ho], &Vh[(size_t)kvr * DEP + ho]);
    }
    CP_COMMIT();
    {
        __half* K1 = smh + 9216 + 4608;
        __half* V1 = smh + 23040 + 4608;
#pragma unroll
        for (int i = 0; i < 2; i++) {
            const int ho = 8 * c4 + 32 * i;
            cp16(&K1[kvr * 72 + ho], &Kh[(size_t)(64 + kvr) * DEP + ho]);
            cp16(&V1[kvr * 72 + ho], &Vh[(size_t)(64 + kvr) * DEP + ho]);
        }
        CP_COMMIT();
    }
    CP_WAIT1();
    __syncthreads();

    unsigned qa[4][4];
#pragma unroll
    for (int ks = 0; ks < 4; ks++) ldsm4(qa[ks], qpA + ks * 32);

    float ctx[8][4];
#pragma unroll
    for (int nt = 0; nt < 8; nt++)
#pragma unroll
        for (int c = 0; c < 4; c++) ctx[nt][c] = 0.f;

    const int ctmax = 2 * rt + 1;
    const float C = 0.18033688f;

    for (int ct = 0; ct <= ctmax; ct++) {
        if (ct + 2 <= ctmax) {
            const int st = (ct + 2) % 3;
            __half* Kn = smh + 9216 + st * 4608;
            __half* Vn = smh + 23040 + st * 4608;
            const size_t gr = (size_t)((ct + 2) * 64 + kvr) * DEP;
#pragma unroll
            for (int i = 0; i < 2; i++) {
                const int ho = 8 * c4 + 32 * i;
                cp16(&Kn[kvr * 72 + ho], &Kh[gr + ho]);
                cp16(&Vn[kvr * 72 + ho], &Vh[gr + ho]);
            }
            CP_COMMIT();
        }

        const int st = ct % 3;
        const unsigned Kbp = kbase + st * 4608 * 2;
        const unsigned Vbp = vbase + st * 4608 * 2;

        // GEMM1: S = Q K^T
        float s[8][4];
#pragma unroll
        for (int nt = 0; nt < 8; nt++)
#pragma unroll
            for (int c = 0; c < 4; c++) s[nt][c] = 0.f;
#pragma unroll
        for (int ks = 0; ks < 4; ks++) {
#pragma unroll
            for (int ntp = 0; ntp < 4; ntp++) {
                unsigned bk[4];
                ldsm4(bk, Kbp + ntp * 2304 + ks * 32 + offK);
                mma_f16(s[2 * ntp],     qa[ks], bk);
                mma_f16(s[2 * ntp + 1], qa[ks], bk + 2);
            }
        }

        // exp * inv (normalized); store fp32; stage fp16 (normalized)
#pragma unroll
        for (int nt = 0; nt < 8; nt++) {
            const int cj = ct * 64 + nt * 8 + 2 * t;
            float e00 = (cj     <= gi0) ? ex2(s[nt][0] * C) * inv0 : 0.f;
            float e01 = (cj + 1 <= gi0) ? ex2(s[nt][1] * C) * inv0 : 0.f;
            float e10 = (cj     <= gi1) ? ex2(s[nt][2] * C) * inv1 : 0.f;
            float e11 = (cj + 1 <= gi1) ? ex2(s[nt][3] * C) * inv1 : 0.f;
            if (write_attn) {
                __stcs((float2*)&attn_out[((size_t)bh * SS_ + gi0) * SS_ + cj],
                       make_float2(e00, e01));
                __stcs((float2*)&attn_out[((size_t)bh * SS_ + gi1) * SS_ + cj],
                       make_float2(e10, e11));
            }
            *(__half2*)&Qs[(w * 16 + g) * 72 + nt * 8 + 2 * t]     = __floats2half2_rn(e00, e01);
            *(__half2*)&Qs[(w * 16 + g + 8) * 72 + nt * 8 + 2 * t] = __floats2half2_rn(e10, e11);
        }
        __syncwarp();

        // GEMM2: ctx += P V
#pragma unroll
        for (int ks = 0; ks < 4; ks++) {
            unsigned pa[4];
            ldsm4(pa, qpA + ks * 32);
#pragma unroll
            for (int ntp = 0; ntp < 4; ntp++) {
                unsigned bv[4];
                ldsm4t(bv, Vbp + ks * 2304 + ntp * 32 + offA);
                mma_f16(ctx[2 * ntp],     pa, bv);
                mma_f16(ctx[2 * ntp + 1], pa, bv + 2);
            }
        }

        if (ct < ctmax) {
            if (ct + 2 <= ctmax) { CP_WAIT1(); } else { CP_WAIT0(); }
            __syncthreads();
        }
    }

    // Store ctx as fp16
    const int b = bh >> 3, h = bh & 7;
#pragma unroll
    for (int nt = 0; nt < 8; nt++) {
        const int d = nt * 8 + 2 * t;
        *(__half2*)&g_ctxh[((size_t)(b * SS_ + gi0)) * DD + h * 64 + d] =
            __floats2half2_rn(ctx[nt][0], ctx[nt][1]);
        *(__half2*)&g_ctxh[((size_t)(b * SS_ + gi1)) * DD + h * 64 + d] =
            __floats2half2_rn(ctx[nt][2], ctx[nt][3]);
    }
}

// ---------------------------------------------------------------------------
extern "C" void kernel_launch(void* const* d_in, const int* in_sizes, int n_in,
                              void* d_out, int out_size) {
    const float* q  = (const float*)d_in[2];
    const float* k  = (const float*)d_in[0];
    const float* v  = (const float*)d_in[1];
    const float* Wq = (const float*)d_in[4];
    const float* bq = (const float*)d_in[5];
    const float* Wk = (const float*)d_in[6];
    const float* bk = (const float*)d_in[7];
    const float* Wv = (const float*)d_in[8];
    const float* bv = (const float*)d_in[9];
    const float* Wo = (const float*)d_in[10];
    const float* bo = (const float*)d_in[11];

    float* out = (float*)d_out;
    const size_t BSD = (size_t)BB * SS_ * DD;
    const size_t ATT = (size_t)BH * SS_ * SS_;

    float* out_main = nullptr;
    float* attn_out = nullptr;
    if ((size_t)out_size >= BSD + ATT) {
        out_main = out;
        attn_out = out + BSD;
    } else if ((size_t)out_size >= ATT) {
        attn_out = out;
    } else {
        out_main = out;
    }

    void *pxq, *pxk, *pxv, *pwq, *pwk, *pwv, *pwo;
    void *pq, *pk, *pv, *pctx;
    cudaGetSymbolAddress(&pxq, g_xq);
    cudaGetSymbolAddress(&pxk, g_xk);
    cudaGetSymbolAddress(&pxv, g_xv);
    cudaGetSymbolAddress(&pwq, g_wq);
    cudaGetSymbolAddress(&pwk, g_wk);
    cudaGetSymbolAddress(&pwv, g_wv);
    cudaGetSymbolAddress(&pwo, g_wo);
    cudaGetSymbolAddress(&pq, g_qh);
    cudaGetSymbolAddress(&pk, g_kh);
    cudaGetSymbolAddress(&pv, g_vh);
    cudaGetSymbolAddress(&pctx, g_ctxh);

    cudaFuncSetAttribute(attn_kernel,
                         cudaFuncAttributeMaxDynamicSharedMemorySize, 73728);
    cudaFuncSetAttribute(rowsum_kernel,
                         cudaFuncAttributeMaxDynamicSharedMemorySize, 46080);
    cudaFuncSetAttribute(gemm_f16k<0>,
                         cudaFuncAttributeMaxDynamicSharedMemorySize, 37888);
    cudaFuncSetAttribute(gemm_f16k<1>,
                         cudaFuncAttributeMaxDynamicSharedMemorySize, 37888);

    // fp32 -> fp16 conversions
    f32to16<<<4096, 256>>>(q,  (__half*)pxq);
    f32to16<<<4096, 256>>>(k,  (__half*)pxk);
    f32to16<<<4096, 256>>>(v,  (__half*)pxv);
    f32to16<<<256,  256>>>(Wq, (__half*)pwq);
    f32to16<<<256,  256>>>(Wk, (__half*)pwk);
    f32to16<<<256,  256>>>(Wv, (__half*)pwv);
    f32to16<<<256,  256>>>(Wo, (__half*)pwo);

    dim3 ggrid(4, 64);
    gemm_f16k<1><<<ggrid, 256, 37888>>>((const __half*)pxq, (const __half*)pwq, bq, (float*)pq);
    gemm_f16k<1><<<ggrid, 256, 37888>>>((const __half*)pxk, (const __half*)pwk, bk, (float*)pk);
    gemm_f16k<1><<<ggrid, 256, 37888>>>((const __half*)pxv, (const __half*)pwv, bv, (float*)pv);

    rowsum_kernel<<<dim3(32, BH), 256, 46080>>>(attn_out, attn_out != nullptr);

    attn_kernel<<<dim3(32, BH), 256, 73728>>>(attn_out, attn_out != nullptr);

    if (out_main) {
        gemm_f16k<0><<<ggrid, 256, 37888>>>((const __half*)pctx, (const __half*)pwo, bo, out_main);
    }
}

// round 16
// speedup vs baseline: 1.1114x; 1.0210x over previous
#include <cuda_runtime.h>
#include <cuda_fp16.h>
#include <math.h>

// Problem constants
#define BB   2
#define SS_  4096
#define DD   512
#define HH   8
#define DEP  64
#define BH   16
#define MM   8192

// fp16 copies of inputs/weights
__device__ __half g_xq[MM * DD];
__device__ __half g_xk[MM * DD];
__device__ __half g_xv[MM * DD];
__device__ __half g_wq[DD * DD];
__device__ __half g_wk[DD * DD];
__device__ __half g_wv[DD * DD];
__device__ __half g_wo[DD * DD];
// Q/K/V head-split [bh][s][d] fp16; ctx fp16 row-major.
__device__ __half g_qh[BH * SS_ * DEP];
__device__ __half g_kh[BH * SS_ * DEP];
__device__ __half g_vh[BH * SS_ * DEP];
__device__ __half g_ctxh[MM * DD];
__device__ float  g_inv[BH * SS_];

struct GemmBatch {
    const __half* X[3];
    const __half* W[3];
    const float*  bias[3];
    float*        Y[3];
};

__device__ __forceinline__ float ex2(float x) {
    float y;
    asm("ex2.approx.ftz.f32 %0, %1;" : "=f"(y) : "f"(x));
    return y;
}

__device__ __forceinline__ void mma_f16(float* d, const unsigned* a, const unsigned* b) {
    asm volatile(
        "mma.sync.aligned.m16n8k16.row.col.f32.f16.f16.f32 "
        "{%0,%1,%2,%3}, {%4,%5,%6,%7}, {%8,%9}, {%0,%1,%2,%3};"
        : "+f"(d[0]), "+f"(d[1]), "+f"(d[2]), "+f"(d[3])
        : "r"(a[0]), "r"(a[1]), "r"(a[2]), "r"(a[3]), "r"(b[0]), "r"(b[1]));
}

__device__ __forceinline__ void ldsm4(unsigned* r, unsigned a) {
    asm volatile("ldmatrix.sync.aligned.m8n8.x4.shared.b16 {%0,%1,%2,%3}, [%4];"
                 : "=r"(r[0]), "=r"(r[1]), "=r"(r[2]), "=r"(r[3]) : "r"(a));
}
__device__ __forceinline__ void ldsm4t(unsigned* r, unsigned a) {
    asm volatile("ldmatrix.sync.aligned.m8n8.x4.trans.shared.b16 {%0,%1,%2,%3}, [%4];"
                 : "=r"(r[0]), "=r"(r[1]), "=r"(r[2]), "=r"(r[3]) : "r"(a));
}

__device__ __forceinline__ void cp16(void* smem_ptr, const void* gptr) {
    unsigned s = (unsigned)__cvta_generic_to_shared(smem_ptr);
    asm volatile("cp.async.cg.shared.global [%0], [%1], 16;" :: "r"(s), "l"(gptr));
}
#define CP_COMMIT() asm volatile("cp.async.commit_group;" ::: "memory")
#define CP_WAIT0()  asm volatile("cp.async.wait_group 0;" ::: "memory")
#define CP_WAIT1()  asm volatile("cp.async.wait_group 1;" ::: "memory")

// ---------------------------------------------------------------------------
// Fused fp32->fp16 converts: activations (3 tensors x 4096 blocks) and
// weights (4 tensors x 256 blocks) each in ONE launch.
// ---------------------------------------------------------------------------
__device__ __forceinline__ void cvt_blk(const float* __restrict__ src,
                                        __half* __restrict__ dst, int bi) {
    const int i = bi * 256 + threadIdx.x;   // float4 index
    float4 v = __ldcs(&((const float4*)src)[i]);
    __half2 a = __floats2half2_rn(v.x, v.y);
    __half2 b = __floats2half2_rn(v.z, v.w);
    uint2 u;
    u.x = *(unsigned*)&a; u.y = *(unsigned*)&b;
    *(uint2*)&dst[(size_t)i * 4] = u;
}

__global__ void __launch_bounds__(256)
f32to16_act(const float* __restrict__ s0, const float* __restrict__ s1,
            const float* __restrict__ s2,
            __half* __restrict__ d0, __half* __restrict__ d1,
            __half* __restrict__ d2) {
    const int which = blockIdx.x >> 12;         // /4096
    const int bi = blockIdx.x & 4095;
    if (which == 0)      cvt_blk(s0, d0, bi);
    else if (which == 1) cvt_blk(s1, d1, bi);
    else                 cvt_blk(s2, d2, bi);
}

__global__ void __launch_bounds__(256)
f32to16_wts(const float* __restrict__ s0, const float* __restrict__ s1,
            const float* __restrict__ s2, const float* __restrict__ s3,
            __half* __restrict__ d0, __half* __restrict__ d1,
            __half* __restrict__ d2, __half* __restrict__ d3) {
    const int which = blockIdx.x >> 8;          // /256
    const int bi = blockIdx.x & 255;
    if (which == 0)      cvt_blk(s0, d0, bi);
    else if (which == 1) cvt_blk(s1, d1, bi);
    else if (which == 2) cvt_blk(s2, d2, bi);
    else                 cvt_blk(s3, d3, bi);
}

// ---------------------------------------------------------------------------
// fp16 GEMM: Y(8192x512) = Xh @ Wh + bias.  m16n8k16, ldmatrix, cp.async x2.
// Batched over gridDim.z via GemmBatch.
// MODE 0: fp32 row-major out. MODE 1: head-split [bh][s][d] fp16 out.
// ---------------------------------------------------------------------------
template <int MODE>
__global__ void __launch_bounds__(256, 2)
gemm_f16k(GemmBatch batch) {
    const __half* __restrict__ X = batch.X[blockIdx.z];
    const __half* __restrict__ W = batch.W[blockIdx.z];
    const float*  __restrict__ bias = batch.bias[blockIdx.z];
    float* __restrict__ Y = batch.Y[blockIdx.z];

    extern __shared__ __half hsm[];
    __half* Xb[2] = {hsm, hsm + 5120};              // [m][k] stride 40
    __half* Wb[2] = {hsm + 10240, hsm + 14592};     // [k][n] stride 136

    const int tid = threadIdx.x;
    const int lane = tid & 31, w = tid >> 5;
    const int g = lane >> 2, t = lane & 3;
    const int wm = w & 3, wn = w >> 2;
    const int m0 = blockIdx.y * 128, n0 = blockIdx.x * 128;

    const unsigned sbase = (unsigned)__cvta_generic_to_shared(hsm);
    const unsigned offA = ((lane & 15) * 40 + (lane >> 4) * 8) * 2;
    const unsigned offB = ((lane & 15) * 136 + (lane >> 4) * 8) * 2;

    float acc[2][8][4];
#pragma unroll
    for (int mt = 0; mt < 2; mt++)
#pragma unroll
        for (int nt = 0; nt < 8; nt++)
#pragma unroll
            for (int c = 0; c < 4; c++) acc[mt][nt][c] = 0.f;

    const int xr = tid >> 1;
    const int xc = (tid & 1) * 16;
    const int wr = tid >> 3;
    const int wc = (tid & 7) * 16;

#pragma unroll
    for (int i = 0; i < 2; i++) {
        cp16(&Xb[0][xr * 40 + xc + i * 8], &X[(size_t)(m0 + xr) * 512 + xc + i * 8]);
        cp16(&Wb[0][wr * 136 + wc + i * 8], &W[(size_t)wr * 512 + n0 + wc + i * 8]);
    }
    CP_COMMIT();
    CP_WAIT0();
    __syncthreads();

    for (int it = 0; it < 16; it++) {
        if (it < 15) {
            const int k0 = (it + 1) * 32;
            __half* Xn = Xb[(it + 1) & 1];
            __half* Wn = Wb[(it + 1) & 1];
#pragma unroll
            for (int i = 0; i < 2; i++) {
                cp16(&Xn[xr * 40 + xc + i * 8], &X[(size_t)(m0 + xr) * 512 + k0 + xc + i * 8]);
                cp16(&Wn[wr * 136 + wc + i * 8], &W[(size_t)(k0 + wr) * 512 + n0 + wc + i * 8]);
            }
            CP_COMMIT();
        }
        const unsigned Xp = sbase + (it & 1) * 5120 * 2;
        const unsigned Wp = sbase + 10240 * 2 + (it & 1) * 4352 * 2;

#pragma unroll
        for (int ks = 0; ks < 2; ks++) {
            unsigned a[2][4];
#pragma unroll
            for (int mt = 0; mt < 2; mt++)
                ldsm4(a[mt], Xp + ((wm * 32 + mt * 16) * 40 + ks * 16) * 2 + offA);
#pragma unroll
            for (int ntp = 0; ntp < 4; ntp++) {
                unsigned bv[4];
                ldsm4t(bv, Wp + (ks * 16 * 136 + wn * 64 + ntp * 16) * 2 + offB);
#pragma unroll
                for (int mt = 0; mt < 2; mt++) {
                    mma_f16(acc[mt][2 * ntp],     a[mt], bv);
                    mma_f16(acc[mt][2 * ntp + 1], a[mt], bv + 2);
                }
            }
        }
        if (it < 15) {
            CP_WAIT0();
            __syncthreads();
        }
    }

    __half* Yh = (__half*)Y;
#pragma unroll
    for (int nt = 0; nt < 8; nt++) {
        const int colg = n0 + wn * 64 + nt * 8 + 2 * t;
        const float b0 = bias[colg], b1 = bias[colg + 1];
#pragma unroll
        for (int mt = 0; mt < 2; mt++) {
            const int rbase = m0 + wm * 32 + mt * 16;
#pragma unroll
            for (int half_ = 0; half_ < 2; half_++) {
                const int r = rbase + g + half_ * 8;
                float ox = acc[mt][nt][half_ * 2 + 0] + b0;
                float oy = acc[mt][nt][half_ * 2 + 1] + b1;
                if (MODE == 0) {
                    *(float2*)&Y[(size_t)r * 512 + colg] = make_float2(ox, oy);
                } else {
                    const int b = r >> 12, s = r & 4095;
                    const int h = colg >> 6, din = colg & 63;
                    *(__half2*)&Yh[(((size_t)(b * 8 + h)) * SS_ + s) * DEP + din] =
                        __floats2half2_rn(ox, oy);
                }
            }
        }
    }
}

// ---------------------------------------------------------------------------
// Rowsum prepass: GEMM1 replay (Q K^T, exp, causal) -> g_inv.
// Epilogue: zero-fill attn upper triangle for this block's rows.
// ---------------------------------------------------------------------------
__global__ void __launch_bounds__(256)
rowsum_kernel(float* __restrict__ attn_out, int write_attn) {
    extern __shared__ __half smh[];
    __half* Qs = smh;

    const int tid = threadIdx.x;
    const int lane = tid & 31, w = tid >> 5;
    const int g = lane >> 2, t = lane & 3;
    const int rt = 31 - blockIdx.x;
    const int bh = blockIdx.y;
    const int row0 = rt * 128;

    const __half* __restrict__ Qh = g_qh + (size_t)bh * SS_ * DEP;
    const __half* __restrict__ Kh = g_kh + (size_t)bh * SS_ * DEP;

    const unsigned sbase = (unsigned)__cvta_generic_to_shared(smh);
    const unsigned kbase = sbase + 9216 * 2;

    const unsigned offA = (((lane & 15) * 72 + (lane >> 4) * 8) * 2);
    const unsigned offK = ((((lane >> 4) * 8 + (lane & 7)) * 72 + ((lane >> 3) & 1) * 8) * 2);
    const unsigned qpA = sbase + (w * 16 * 72) * 2 + offA;

    const int kvr = tid >> 2;
    const int c4 = tid & 3;

    {
        const int qr = tid >> 1;
        const int qo = (tid & 1) * 32;
#pragma unroll
        for (int i = 0; i < 4; i++)
            cp16(&Qs[qr * 72 + qo + i * 8], &Qh[(size_t)(row0 + qr) * DEP + qo + i * 8]);
    }
    __half* K0 = smh + 9216;
#pragma unroll
    for (int i = 0; i < 2; i++) {
        const int ho = 8 * c4 + 32 * i;
        cp16(&K0[kvr * 72 + ho], &Kh[(size_t)kvr * DEP + ho]);
    }
    CP_COMMIT();
    {
        __half* K1 = smh + 9216 + 4608;
#pragma unroll
        for (int i = 0; i < 2; i++) {
            const int ho = 8 * c4 + 32 * i;
            cp16(&K1[kvr * 72 + ho], &Kh[(size_t)(64 + kvr) * DEP + ho]);
        }
        CP_COMMIT();
    }
    CP_WAIT1();
    __syncthreads();

    unsigned qa[4][4];
#pragma unroll
    for (int ks = 0; ks < 4; ks++) ldsm4(qa[ks], qpA + ks * 32);

    float rs0 = 0.f, rs1 = 0.f;
    const int gi0 = row0 + w * 16 + g;
    const int gi1 = gi0 + 8;
    const int ctmax = 2 * rt + 1;
    const float C = 0.18033688f;  // 0.125 * log2(e)

    for (int ct = 0; ct <= ctmax; ct++) {
        if (ct + 2 <= ctmax) {
            const int st = (ct + 2) % 3;
            __half* Kn = smh + 9216 + st * 4608;
            const size_t gr = (size_t)((ct + 2) * 64 + kvr) * DEP;
#pragma unroll
            for (int i = 0; i < 2; i++) {
                const int ho = 8 * c4 + 32 * i;
                cp16(&Kn[kvr * 72 + ho], &Kh[gr + ho]);
            }
            CP_COMMIT();
        }

        const unsigned Kbp = kbase + (ct % 3) * 4608 * 2;

        float s[8][4];
#pragma unroll
        for (int nt = 0; nt < 8; nt++)
#pragma unroll
            for (int c = 0; c < 4; c++) s[nt][c] = 0.f;
#pragma unroll
        for (int ks = 0; ks < 4; ks++) {
#pragma unroll
            for (int ntp = 0; ntp < 4; ntp++) {
                unsigned bk[4];
                ldsm4(bk, Kbp + ntp * 2304 + ks * 32 + offK);
                mma_f16(s[2 * ntp],     qa[ks], bk);
                mma_f16(s[2 * ntp + 1], qa[ks], bk + 2);
            }
        }

#pragma unroll
        for (int nt = 0; nt < 8; nt++) {
            const int cj = ct * 64 + nt * 8 + 2 * t;
            rs0 += (cj     <= gi0) ? ex2(s[nt][0] * C) : 0.f;
            rs0 += (cj + 1 <= gi0) ? ex2(s[nt][1] * C) : 0.f;
            rs1 += (cj     <= gi1) ? ex2(s[nt][2] * C) : 0.f;
            rs1 += (cj + 1 <= gi1) ? ex2(s[nt][3] * C) : 0.f;
        }

        if (ct < ctmax) {
            if (ct + 2 <= ctmax) { CP_WAIT1(); } else { CP_WAIT0(); }
            __syncthreads();
        }
    }

    rs0 += __shfl_xor_sync(0xffffffffu, rs0, 1);
    rs0 += __shfl_xor_sync(0xffffffffu, rs0, 2);
    rs1 += __shfl_xor_sync(0xffffffffu, rs1, 1);
    rs1 += __shfl_xor_sync(0xffffffffu, rs1, 2);
    if (t == 0) {
        g_inv[(size_t)bh * SS_ + gi0] = 1.f / rs0;
        g_inv[(size_t)bh * SS_ + gi1] = 1.f / rs1;
    }

    // Epilogue: zero-fill upper triangle for this block's rows
    if (write_attn) {
        const int c0 = (rt + 1) * 128;
        const float4 z4 = make_float4(0.f, 0.f, 0.f, 0.f);
#pragma unroll 1
        for (int rr = 0; rr < 16; rr++) {
            float* rowp = attn_out + ((size_t)bh * SS_ + row0 + w * 16 + rr) * SS_;
            for (int c = c0 + lane * 4; c < SS_; c += 128)
                __stcs((float4*)(rowp + c), z4);
        }
    }
}

// ---------------------------------------------------------------------------
// Causal flash attention. Writes NORMALIZED P and fp16 ctx.
// ---------------------------------------------------------------------------
__global__ void __launch_bounds__(256, 2)
attn_kernel(float* __restrict__ attn_out, int write_attn) {
    extern __shared__ __half smh[];
    __half* Qs = smh;

    const int tid = threadIdx.x;
    const int lane = tid & 31, w = tid >> 5;
    const int g = lane >> 2, t = lane & 3;
    const int rt = 31 - blockIdx.x;
    const int bh = blockIdx.y;
    const int row0 = rt * 128;

    const __half* __restrict__ Qh = g_qh + (size_t)bh * SS_ * DEP;
    const __half* __restrict__ Kh = g_kh + (size_t)bh * SS_ * DEP;
    const __half* __restrict__ Vh = g_vh + (size_t)bh * SS_ * DEP;

    const unsigned sbase = (unsigned)__cvta_generic_to_shared(smh);
    const unsigned kbase = sbase + 9216 * 2;
    const unsigned vbase = sbase + 23040 * 2;

    const unsigned offA = (((lane & 15) * 72 + (lane >> 4) * 8) * 2);
    const unsigned offK = ((((lane >> 4) * 8 + (lane & 7)) * 72 + ((lane >> 3) & 1) * 8) * 2);
    const unsigned qpA = sbase + (w * 16 * 72) * 2 + offA;

    const int kvr = tid >> 2;
    const int c4 = tid & 3;

    const int gi0 = row0 + w * 16 + g;
    const int gi1 = gi0 + 8;

    const float inv0 = g_inv[(size_t)bh * SS_ + gi0];
    const float inv1 = g_inv[(size_t)bh * SS_ + gi1];

    {
        const int qr = tid >> 1;
        const int qo = (tid & 1) * 32;
#pragma unroll
        for (int i = 0; i < 4; i++)
            cp16(&Qs[qr * 72 + qo + i * 8], &Qh[(size_t)(row0 + qr) * DEP + qo + i * 8]);
    }
    __half* K0 = smh + 9216;
    __half* V0 = smh + 23040;
#pragma unroll
    for (int i = 0; i < 2; i++) {
        const int ho = 8 * c4 + 32 * i;
        cp16(&K0[kvr * 72 + ho], &Kh[(size_t)kvr * DEP + ho]);
        cp16(&V0[kvr * 72 + ho], &Vh[(size_t)kvr * DEP + ho]);
    }
    CP_COMMIT();
    {
        __half* K1 = smh + 9216 + 4608;
        __half* V1 = smh + 23040 + 4608;
#pragma unroll
        for (int i = 0; i < 2; i++) {
            const int ho = 8 * c4 + 32 * i;
            cp16(&K1[kvr * 72 + ho], &Kh[(size_t)(64 + kvr) * DEP + ho]);
            cp16(&V1[kvr * 72 + ho], &Vh[(size_t)(64 + kvr) * DEP + ho]);
        }
        CP_COMMIT();
    }
    CP_WAIT1();
    __syncthreads();

    unsigned qa[4][4];
#pragma unroll
    for (int ks = 0; ks < 4; ks++) ldsm4(qa[ks], qpA + ks * 32);

    float ctx[8][4];
#pragma unroll
    for (int nt = 0; nt < 8; nt++)
#pragma unroll
        for (int c = 0; c < 4; c++) ctx[nt][c] = 0.f;

    const int ctmax = 2 * rt + 1;
    const float C = 0.18033688f;

    for (int ct = 0; ct <= ctmax; ct++) {
        if (ct + 2 <= ctmax) {
            const int st = (ct + 2) % 3;
            __half* Kn = smh + 9216 + st * 4608;
            __half* Vn = smh + 23040 + st * 4608;
            const size_t gr = (size_t)((ct + 2) * 64 + kvr) * DEP;
#pragma unroll
            for (int i = 0; i < 2; i++) {
                const int ho = 8 * c4 + 32 * i;
                cp16(&Kn[kvr * 72 + ho], &Kh[gr + ho]);
                cp16(&Vn[kvr * 72 + ho], &Vh[gr + ho]);
            }
            CP_COMMIT();
        }

        const int st = ct % 3;
        const unsigned Kbp = kbase + st * 4608 * 2;
        const unsigned Vbp = vbase + st * 4608 * 2;

        // GEMM1: S = Q K^T
        float s[8][4];
#pragma unroll
        for (int nt = 0; nt < 8; nt++)
#pragma unroll
            for (int c = 0; c < 4; c++) s[nt][c] = 0.f;
#pragma unroll
        for (int ks = 0; ks < 4; ks++) {
#pragma unroll
            for (int ntp = 0; ntp < 4; ntp++) {
                unsigned bk[4];
                ldsm4(bk, Kbp + ntp * 2304 + ks * 32 + offK);
                mma_f16(s[2 * ntp],     qa[ks], bk);
                mma_f16(s[2 * ntp + 1], qa[ks], bk + 2);
            }
        }

        // exp * inv (normalized); store fp32; stage fp16 (normalized)
#pragma unroll
        for (int nt = 0; nt < 8; nt++) {
            const int cj = ct * 64 + nt * 8 + 2 * t;
            float e00 = (cj     <= gi0) ? ex2(s[nt][0] * C) * inv0 : 0.f;
            float e01 = (cj + 1 <= gi0) ? ex2(s[nt][1] * C) * inv0 : 0.f;
            float e10 = (cj     <= gi1) ? ex2(s[nt][2] * C) * inv1 : 0.f;
            float e11 = (cj + 1 <= gi1) ? ex2(s[nt][3] * C) * inv1 : 0.f;
            if (write_attn) {
                __stcs((float2*)&attn_out[((size_t)bh * SS_ + gi0) * SS_ + cj],
                       make_float2(e00, e01));
                __stcs((float2*)&attn_out[((size_t)bh * SS_ + gi1) * SS_ + cj],
                       make_float2(e10, e11));
            }
            *(__half2*)&Qs[(w * 16 + g) * 72 + nt * 8 + 2 * t]     = __floats2half2_rn(e00, e01);
            *(__half2*)&Qs[(w * 16 + g + 8) * 72 + nt * 8 + 2 * t] = __floats2half2_rn(e10, e11);
        }
        __syncwarp();

        // GEMM2: ctx += P V
#pragma unroll
        for (int ks = 0; ks < 4; ks++) {
            unsigned pa[4];
            ldsm4(pa, qpA + ks * 32);
#pragma unroll
            for (int ntp = 0; ntp < 4; ntp++) {
                unsigned bv[4];
                ldsm4t(bv, Vbp + ks * 2304 + ntp * 32 + offA);
                mma_f16(ctx[2 * ntp],     pa, bv);
                mma_f16(ctx[2 * ntp + 1], pa, bv + 2);
            }
        }

        if (ct < ctmax) {
            if (ct + 2 <= ctmax) { CP_WAIT1(); } else { CP_WAIT0(); }
            __syncthreads();
        }
    }

    // Store ctx as fp16
    const int b = bh >> 3, h = bh & 7;
#pragma unroll
    for (int nt = 0; nt < 8; nt++) {
        const int d = nt * 8 + 2 * t;
        *(__half2*)&g_ctxh[((size_t)(b * SS_ + gi0)) * DD + h * 64 + d] =
            __floats2half2_rn(ctx[nt][0], ctx[nt][1]);
        *(__half2*)&g_ctxh[((size_t)(b * SS_ + gi1)) * DD + h * 64 + d] =
            __floats2half2_rn(ctx[nt][2], ctx[nt][3]);
    }
}

// ---------------------------------------------------------------------------
extern "C" void kernel_launch(void* const* d_in, const int* in_sizes, int n_in,
                              void* d_out, int out_size) {
    const float* q  = (const float*)d_in[2];
    const float* k  = (const float*)d_in[0];
    const float* v  = (const float*)d_in[1];
    const float* Wq = (const float*)d_in[4];
    const float* bq = (const float*)d_in[5];
    const float* Wk = (const float*)d_in[6];
    const float* bk = (const float*)d_in[7];
    const float* Wv = (const float*)d_in[8];
    const float* bv = (const float*)d_in[9];
    const float* Wo = (const float*)d_in[10];
    const float* bo = (const float*)d_in[11];

    float* out = (float*)d_out;
    const size_t BSD = (size_t)BB * SS_ * DD;
    const size_t ATT = (size_t)BH * SS_ * SS_;

    float* out_main = nullptr;
    float* attn_out = nullptr;
    if ((size_t)out_size >= BSD + ATT) {
        out_main = out;
        attn_out = out + BSD;
    } else if ((size_t)out_size >= ATT) {
        attn_out = out;
    } else {
        out_main = out;
    }

    void *pxq, *pxk, *pxv, *pwq, *pwk, *pwv, *pwo;
    void *pq, *pk, *pv, *pctx;
    cudaGetSymbolAddress(&pxq, g_xq);
    cudaGetSymbolAddress(&pxk, g_xk);
    cudaGetSymbolAddress(&pxv, g_xv);
    cudaGetSymbolAddress(&pwq, g_wq);
    cudaGetSymbolAddress(&pwk, g_wk);
    cudaGetSymbolAddress(&pwv, g_wv);
    cudaGetSymbolAddress(&pwo, g_wo);
    cudaGetSymbolAddress(&pq, g_qh);
    cudaGetSymbolAddress(&pk, g_kh);
    cudaGetSymbolAddress(&pv, g_vh);
    cudaGetSymbolAddress(&pctx, g_ctxh);

    cudaFuncSetAttribute(attn_kernel,
                         cudaFuncAttributeMaxDynamicSharedMemorySize, 73728);
    cudaFuncSetAttribute(rowsum_kernel,
                         cudaFuncAttributeMaxDynamicSharedMemorySize, 46080);
    cudaFuncSetAttribute(gemm_f16k<0>,
                         cudaFuncAttributeMaxDynamicSharedMemorySize, 37888);
    cudaFuncSetAttribute(gemm_f16k<1>,
                         cudaFuncAttributeMaxDynamicSharedMemorySize, 37888);

    // Fused converts: 2 launches instead of 7
    f32to16_act<<<3 * 4096, 256>>>(q, k, v,
                                   (__half*)pxq, (__half*)pxk, (__half*)pxv);
    f32to16_wts<<<4 * 256, 256>>>(Wq, Wk, Wv, Wo,
                                  (__half*)pwq, (__half*)pwk,
                                  (__half*)pwv, (__half*)pwo);

    // Batched QKV projection: one launch, gridDim.z = 3
    GemmBatch qkv;
    qkv.X[0] = (const __half*)pxq; qkv.W[0] = (const __half*)pwq;
    qkv.bias[0] = bq; qkv.Y[0] = (float*)pq;
    qkv.X[1] = (const __half*)pxk; qkv.W[1] = (const __half*)pwk;
    qkv.bias[1] = bk; qkv.Y[1] = (float*)pk;
    qkv.X[2] = (const __half*)pxv; qkv.W[2] = (const __half*)pwv;
    qkv.bias[2] = bv; qkv.Y[2] = (float*)pv;
    gemm_f16k<1><<<dim3(4, 64, 3), 256, 37888>>>(qkv);

    rowsum_kernel<<<dim3(32, BH), 256, 46080>>>(attn_out, attn_out != nullptr);

    attn_kernel<<<dim3(32, BH), 256, 73728>>>(attn_out, attn_out != nullptr);

    if (out_main) {
        GemmBatch ob;
        ob.X[0] = (const __half*)pctx; ob.W[0] = (const __half*)pwo;
        ob.bias[0] = bo; ob.Y[0] = out_main;
        ob.X[1] = ob.X[0]; ob.W[1] = ob.W[0]; ob.bias[1] = ob.bias[0]; ob.Y[1] = ob.Y[0];
        ob.X[2] = ob.X[0]; ob.W[2] = ob.W[0]; ob.bias[2] = ob.bias[0]; ob.Y[2] = ob.Y[0];
        gemm_f16k<0><<<dim3(4, 64, 1), 256, 37888>>>(ob);
    }
}

// round 17
// speedup vs baseline: 1.1364x; 1.0225x over previous
#include <cuda_runtime.h>
#include <cuda_fp16.h>
#include <math.h>

// Problem constants
#define BB   2
#define SS_  4096
#define DD   512
#define HH   8
#define DEP  64
#define BH   16
#define MM   8192

// fp16 copies of inputs/weights
__device__ __half g_xq[MM * DD];
__device__ __half g_xk[MM * DD];
__device__ __half g_xv[MM * DD];
__device__ __half g_wq[DD * DD];
__device__ __half g_wk[DD * DD];
__device__ __half g_wv[DD * DD];
__device__ __half g_wo[DD * DD];
// Q/K/V head-split [bh][s][d] fp16; ctx fp16 row-major.
__device__ __half g_qh[BH * SS_ * DEP];
__device__ __half g_kh[BH * SS_ * DEP];
__device__ __half g_vh[BH * SS_ * DEP];
__device__ __half g_ctxh[MM * DD];

struct GemmBatch {
    const __half* X[3];
    const __half* W[3];
    const float*  bias[3];
    float*        Y[3];
};

__device__ __forceinline__ float ex2(float x) {
    float y;
    asm("ex2.approx.ftz.f32 %0, %1;" : "=f"(y) : "f"(x));
    return y;
}

__device__ __forceinline__ void mma_f16(float* d, const unsigned* a, const unsigned* b) {
    asm volatile(
        "mma.sync.aligned.m16n8k16.row.col.f32.f16.f16.f32 "
        "{%0,%1,%2,%3}, {%4,%5,%6,%7}, {%8,%9}, {%0,%1,%2,%3};"
        : "+f"(d[0]), "+f"(d[1]), "+f"(d[2]), "+f"(d[3])
        : "r"(a[0]), "r"(a[1]), "r"(a[2]), "r"(a[3]), "r"(b[0]), "r"(b[1]));
}

__device__ __forceinline__ void ldsm4(unsigned* r, unsigned a) {
    asm volatile("ldmatrix.sync.aligned.m8n8.x4.shared.b16 {%0,%1,%2,%3}, [%4];"
                 : "=r"(r[0]), "=r"(r[1]), "=r"(r[2]), "=r"(r[3]) : "r"(a));
}
__device__ __forceinline__ void ldsm4t(unsigned* r, unsigned a) {
    asm volatile("ldmatrix.sync.aligned.m8n8.x4.trans.shared.b16 {%0,%1,%2,%3}, [%4];"
                 : "=r"(r[0]), "=r"(r[1]), "=r"(r[2]), "=r"(r[3]) : "r"(a));
}

__device__ __forceinline__ void cp16(void* smem_ptr, const void* gptr) {
    unsigned s = (unsigned)__cvta_generic_to_shared(smem_ptr);
    asm volatile("cp.async.cg.shared.global [%0], [%1], 16;" :: "r"(s), "l"(gptr));
}
#define CP_COMMIT() asm volatile("cp.async.commit_group;" ::: "memory")
#define CP_WAIT0()  asm volatile("cp.async.wait_group 0;" ::: "memory")
#define CP_WAIT1()  asm volatile("cp.async.wait_group 1;" ::: "memory")

// ---------------------------------------------------------------------------
// Fused fp32->fp16 converts
// ---------------------------------------------------------------------------
__device__ __forceinline__ void cvt_blk(const float* __restrict__ src,
                                        __half* __restrict__ dst, int bi) {
    const int i = bi * 256 + threadIdx.x;   // float4 index
    float4 v = __ldcs(&((const float4*)src)[i]);
    __half2 a = __floats2half2_rn(v.x, v.y);
    __half2 b = __floats2half2_rn(v.z, v.w);
    uint2 u;
    u.x = *(unsigned*)&a; u.y = *(unsigned*)&b;
    *(uint2*)&dst[(size_t)i * 4] = u;
}

__global__ void __launch_bounds__(256)
f32to16_act(const float* __restrict__ s0, const float* __restrict__ s1,
            const float* __restrict__ s2,
            __half* __restrict__ d0, __half* __restrict__ d1,
            __half* __restrict__ d2) {
    const int which = blockIdx.x >> 12;
    const int bi = blockIdx.x & 4095;
    if (which == 0)      cvt_blk(s0, d0, bi);
    else if (which == 1) cvt_blk(s1, d1, bi);
    else                 cvt_blk(s2, d2, bi);
}

__global__ void __launch_bounds__(256)
f32to16_wts(const float* __restrict__ s0, const float* __restrict__ s1,
            const float* __restrict__ s2, const float* __restrict__ s3,
            __half* __restrict__ d0, __half* __restrict__ d1,
            __half* __restrict__ d2, __half* __restrict__ d3) {
    const int which = blockIdx.x >> 8;
    const int bi = blockIdx.x & 255;
    if (which == 0)      cvt_blk(s0, d0, bi);
    else if (which == 1) cvt_blk(s1, d1, bi);
    else if (which == 2) cvt_blk(s2, d2, bi);
    else                 cvt_blk(s3, d3, bi);
}

// ---------------------------------------------------------------------------
// fp16 GEMM: Y(8192x512) = Xh @ Wh + bias. Batched over gridDim.z.
// MODE 0: fp32 row-major out. MODE 1: head-split [bh][s][d] fp16 out.
// ---------------------------------------------------------------------------
template <int MODE>
__global__ void __launch_bounds__(256, 2)
gemm_f16k(GemmBatch batch) {
    const __half* __restrict__ X = batch.X[blockIdx.z];
    const __half* __restrict__ W = batch.W[blockIdx.z];
    const float*  __restrict__ bias = batch.bias[blockIdx.z];
    float* __restrict__ Y = batch.Y[blockIdx.z];

    extern __shared__ __half hsm[];
    __half* Xb[2] = {hsm, hsm + 5120};              // [m][k] stride 40
    __half* Wb[2] = {hsm + 10240, hsm + 14592};     // [k][n] stride 136

    const int tid = threadIdx.x;
    const int lane = tid & 31, w = tid >> 5;
    const int g = lane >> 2, t = lane & 3;
    const int wm = w & 3, wn = w >> 2;
    const int m0 = blockIdx.y * 128, n0 = blockIdx.x * 128;

    const unsigned sbase = (unsigned)__cvta_generic_to_shared(hsm);
    const unsigned offA = ((lane & 15) * 40 + (lane >> 4) * 8) * 2;
    const unsigned offB = ((lane & 15) * 136 + (lane >> 4) * 8) * 2;

    float acc[2][8][4];
#pragma unroll
    for (int mt = 0; mt < 2; mt++)
#pragma unroll
        for (int nt = 0; nt < 8; nt++)
#pragma unroll
            for (int c = 0; c < 4; c++) acc[mt][nt][c] = 0.f;

    const int xr = tid >> 1;
    const int xc = (tid & 1) * 16;
    const int wr = tid >> 3;
    const int wc = (tid & 7) * 16;

#pragma unroll
    for (int i = 0; i < 2; i++) {
        cp16(&Xb[0][xr * 40 + xc + i * 8], &X[(size_t)(m0 + xr) * 512 + xc + i * 8]);
        cp16(&Wb[0][wr * 136 + wc + i * 8], &W[(size_t)wr * 512 + n0 + wc + i * 8]);
    }
    CP_COMMIT();
    CP_WAIT0();
    __syncthreads();

    for (int it = 0; it < 16; it++) {
        if (it < 15) {
            const int k0 = (it + 1) * 32;
            __half* Xn = Xb[(it + 1) & 1];
            __half* Wn = Wb[(it + 1) & 1];
#pragma unroll
            for (int i = 0; i < 2; i++) {
                cp16(&Xn[xr * 40 + xc + i * 8], &X[(size_t)(m0 + xr) * 512 + k0 + xc + i * 8]);
                cp16(&Wn[wr * 136 + wc + i * 8], &W[(size_t)(k0 + wr) * 512 + n0 + wc + i * 8]);
            }
            CP_COMMIT();
        }
        const unsigned Xp = sbase + (it & 1) * 5120 * 2;
        const unsigned Wp = sbase + 10240 * 2 + (it & 1) * 4352 * 2;

#pragma unroll
        for (int ks = 0; ks < 2; ks++) {
            unsigned a[2][4];
#pragma unroll
            for (int mt = 0; mt < 2; mt++)
                ldsm4(a[mt], Xp + ((wm * 32 + mt * 16) * 40 + ks * 16) * 2 + offA);
#pragma unroll
            for (int ntp = 0; ntp < 4; ntp++) {
                unsigned bv[4];
                ldsm4t(bv, Wp + (ks * 16 * 136 + wn * 64 + ntp * 16) * 2 + offB);
#pragma unroll
                for (int mt = 0; mt < 2; mt++) {
                    mma_f16(acc[mt][2 * ntp],     a[mt], bv);
                    mma_f16(acc[mt][2 * ntp + 1], a[mt], bv + 2);
                }
            }
        }
        if (it < 15) {
            CP_WAIT0();
            __syncthreads();
        }
    }

    __half* Yh = (__half*)Y;
#pragma unroll
    for (int nt = 0; nt < 8; nt++) {
        const int colg = n0 + wn * 64 + nt * 8 + 2 * t;
        const float b0 = bias[colg], b1 = bias[colg + 1];
#pragma unroll
        for (int mt = 0; mt < 2; mt++) {
            const int rbase = m0 + wm * 32 + mt * 16;
#pragma unroll
            for (int half_ = 0; half_ < 2; half_++) {
                const int r = rbase + g + half_ * 8;
                float ox = acc[mt][nt][half_ * 2 + 0] + b0;
                float oy = acc[mt][nt][half_ * 2 + 1] + b1;
                if (MODE == 0) {
                    *(float2*)&Y[(size_t)r * 512 + colg] = make_float2(ox, oy);
                } else {
                    const int b = r >> 12, s = r & 4095;
                    const int h = colg >> 6, din = colg & 63;
                    *(__half2*)&Yh[(((size_t)(b * 8 + h)) * SS_ + s) * DEP + din] =
                        __floats2half2_rn(ox, oy);
                }
            }
        }
    }
}

// ---------------------------------------------------------------------------
// FUSED causal flash attention:
//   Sweep 1: GEMM1-only over causal width -> rowsums -> inv (registers only).
//   Zero-fill upper triangle for this block's rows.
//   Sweep 2: GEMM1 + normalized P writes + GEMM2 -> fp16 ctx.
// smem halves: Qs[128*72]=9216 (reused as Ps in sweep 2),
//              K ring 3x[64*72] @9216, V ring 3x[64*72] @23040 => 73728 B.
// ---------------------------------------------------------------------------
__global__ void __launch_bounds__(256, 2)
attn_fused(float* __restrict__ attn_out, int write_attn) {
    extern __shared__ __half smh[];
    __half* Qs = smh;

    const int tid = threadIdx.x;
    const int lane = tid & 31, w = tid >> 5;
    const int g = lane >> 2, t = lane & 3;
    const int rt = 31 - blockIdx.x;     // heavy blocks first
    const int bh = blockIdx.y;
    const int row0 = rt * 128;

    const __half* __restrict__ Qh = g_qh + (size_t)bh * SS_ * DEP;
    const __half* __restrict__ Kh = g_kh + (size_t)bh * SS_ * DEP;
    const __half* __restrict__ Vh = g_vh + (size_t)bh * SS_ * DEP;

    const unsigned sbase = (unsigned)__cvta_generic_to_shared(smh);
    const unsigned kbase = sbase + 9216 * 2;
    const unsigned vbase = sbase + 23040 * 2;

    const unsigned offA = (((lane & 15) * 72 + (lane >> 4) * 8) * 2);
    const unsigned offK = ((((lane >> 4) * 8 + (lane & 7)) * 72 + ((lane >> 3) & 1) * 8) * 2);
    const unsigned qpA = sbase + (w * 16 * 72) * 2 + offA;

    const int kvr = tid >> 2;
    const int c4 = tid & 3;

    const int gi0 = row0 + w * 16 + g;
    const int gi1 = gi0 + 8;
    const int ctmax = 2 * rt + 1;
    const float C = 0.18033688f;  // 0.125 * log2(e)

    // ---- Sweep 1 prologue: Q + K0 (group0), K1 (group1) ----
    {
        const int qr = tid >> 1;
        const int qo = (tid & 1) * 32;
#pragma unroll
        for (int i = 0; i < 4; i++)
            cp16(&Qs[qr * 72 + qo + i * 8], &Qh[(size_t)(row0 + qr) * DEP + qo + i * 8]);
    }
    __half* K0 = smh + 9216;
#pragma unroll
    for (int i = 0; i < 2; i++) {
        const int ho = 8 * c4 + 32 * i;
        cp16(&K0[kvr * 72 + ho], &Kh[(size_t)kvr * DEP + ho]);
    }
    CP_COMMIT();
    {
        __half* K1 = smh + 9216 + 4608;
#pragma unroll
        for (int i = 0; i < 2; i++) {
            const int ho = 8 * c4 + 32 * i;
            cp16(&K1[kvr * 72 + ho], &Kh[(size_t)(64 + kvr) * DEP + ho]);
        }
        CP_COMMIT();
    }
    CP_WAIT1();
    __syncthreads();

    // Q fragments once — persist across BOTH sweeps
    unsigned qa[4][4];
#pragma unroll
    for (int ks = 0; ks < 4; ks++) ldsm4(qa[ks], qpA + ks * 32);

    // ---- Sweep 1: rowsums ----
    float rs0 = 0.f, rs1 = 0.f;
    for (int ct = 0; ct <= ctmax; ct++) {
        if (ct + 2 <= ctmax) {
            const int st = (ct + 2) % 3;
            __half* Kn = smh + 9216 + st * 4608;
            const size_t gr = (size_t)((ct + 2) * 64 + kvr) * DEP;
#pragma unroll
            for (int i = 0; i < 2; i++) {
                const int ho = 8 * c4 + 32 * i;
                cp16(&Kn[kvr * 72 + ho], &Kh[gr + ho]);
            }
            CP_COMMIT();
        }

        const unsigned Kbp = kbase + (ct % 3) * 4608 * 2;

        float s[8][4];
#pragma unroll
        for (int nt = 0; nt < 8; nt++)
#pragma unroll
            for (int c = 0; c < 4; c++) s[nt][c] = 0.f;
#pragma unroll
        for (int ks = 0; ks < 4; ks++) {
#pragma unroll
            for (int ntp = 0; ntp < 4; ntp++) {
                unsigned bk[4];
                ldsm4(bk, Kbp + ntp * 2304 + ks * 32 + offK);
                mma_f16(s[2 * ntp],     qa[ks], bk);
                mma_f16(s[2 * ntp + 1], qa[ks], bk + 2);
            }
        }

#pragma unroll
        for (int nt = 0; nt < 8; nt++) {
            const int cj = ct * 64 + nt * 8 + 2 * t;
            rs0 += (cj     <= gi0) ? ex2(s[nt][0] * C) : 0.f;
            rs0 += (cj + 1 <= gi0) ? ex2(s[nt][1] * C) : 0.f;
            rs1 += (cj     <= gi1) ? ex2(s[nt][2] * C) : 0.f;
            rs1 += (cj + 1 <= gi1) ? ex2(s[nt][3] * C) : 0.f;
        }

        if (ct < ctmax) {
            if (ct + 2 <= ctmax) { CP_WAIT1(); } else { CP_WAIT0(); }
            __syncthreads();
        }
    }

    rs0 += __shfl_xor_sync(0xffffffffu, rs0, 1);
    rs0 += __shfl_xor_sync(0xffffffffu, rs0, 2);
    rs1 += __shfl_xor_sync(0xffffffffu, rs1, 1);
    rs1 += __shfl_xor_sync(0xffffffffu, rs1, 2);
    const float inv0 = 1.f / rs0;
    const float inv1 = 1.f / rs1;

    // Zero-fill upper triangle for this block's rows (balances with compute:
    // fill ∝ 31-rt, compute ∝ rt; stores drain during sweep 2).
    if (write_attn) {
        const int c0 = (rt + 1) * 128;
        const float4 z4 = make_float4(0.f, 0.f, 0.f, 0.f);
#pragma unroll 1
        for (int rr = 0; rr < 16; rr++) {
            float* rowp = attn_out + ((size_t)bh * SS_ + row0 + w * 16 + rr) * SS_;
            for (int c = c0 + lane * 4; c < SS_; c += 128)
                __stcs((float4*)(rowp + c), z4);
        }
    }

    // All warps done reading K ring in sweep 1 before refilling it
    __syncthreads();

    // ---- Sweep 2 prologue: K0+V0 (group0), K1+V1 (group1) ----
#pragma unroll
    for (int i = 0; i < 2; i++) {
        const int ho = 8 * c4 + 32 * i;
        cp16(&K0[kvr * 72 + ho], &Kh[(size_t)kvr * DEP + ho]);
        cp16(&smh[23040 + kvr * 72 + ho], &Vh[(size_t)kvr * DEP + ho]);
    }
    CP_COMMIT();
#pragma unroll
    for (int i = 0; i < 2; i++) {
        const int ho = 8 * c4 + 32 * i;
        cp16(&smh[9216 + 4608 + kvr * 72 + ho], &Kh[(size_t)(64 + kvr) * DEP + ho]);
        cp16(&smh[23040 + 4608 + kvr * 72 + ho], &Vh[(size_t)(64 + kvr) * DEP + ho]);
    }
    CP_COMMIT();
    CP_WAIT1();
    __syncthreads();

    float ctx[8][4];
#pragma unroll
    for (int nt = 0; nt < 8; nt++)
#pragma unroll
        for (int c = 0; c < 4; c++) ctx[nt][c] = 0.f;

    // ---- Sweep 2: full attention ----
    for (int ct = 0; ct <= ctmax; ct++) {
        if (ct + 2 <= ctmax) {
            const int st = (ct + 2) % 3;
            __half* Kn = smh + 9216 + st * 4608;
            __half* Vn = smh + 23040 + st * 4608;
            const size_t gr = (size_t)((ct + 2) * 64 + kvr) * DEP;
#pragma unroll
            for (int i = 0; i < 2; i++) {
                const int ho = 8 * c4 + 32 * i;
                cp16(&Kn[kvr * 72 + ho], &Kh[gr + ho]);
                cp16(&Vn[kvr * 72 + ho], &Vh[gr + ho]);
            }
            CP_COMMIT();
        }

        const int st = ct % 3;
        const unsigned Kbp = kbase + st * 4608 * 2;
        const unsigned Vbp = vbase + st * 4608 * 2;

        // GEMM1: S = Q K^T
        float s[8][4];
#pragma unroll
        for (int nt = 0; nt < 8; nt++)
#pragma unroll
            for (int c = 0; c < 4; c++) s[nt][c] = 0.f;
#pragma unroll
        for (int ks = 0; ks < 4; ks++) {
#pragma unroll
            for (int ntp = 0; ntp < 4; ntp++) {
                unsigned bk[4];
                ldsm4(bk, Kbp + ntp * 2304 + ks * 32 + offK);
                mma_f16(s[2 * ntp],     qa[ks], bk);
                mma_f16(s[2 * ntp + 1], qa[ks], bk + 2);
            }
        }

        // exp * inv (normalized); store fp32; stage fp16 (normalized)
#pragma unroll
        for (int nt = 0; nt < 8; nt++) {
            const int cj = ct * 64 + nt * 8 + 2 * t;
            float e00 = (cj     <= gi0) ? ex2(s[nt][0] * C) * inv0 : 0.f;
            float e01 = (cj + 1 <= gi0) ? ex2(s[nt][1] * C) * inv0 : 0.f;
            float e10 = (cj     <= gi1) ? ex2(s[nt][2] * C) * inv1 : 0.f;
            float e11 = (cj + 1 <= gi1) ? ex2(s[nt][3] * C) * inv1 : 0.f;
            if (write_attn) {
                __stcs((float2*)&attn_out[((size_t)bh * SS_ + gi0) * SS_ + cj],
                       make_float2(e00, e01));
                __stcs((float2*)&attn_out[((size_t)bh * SS_ + gi1) * SS_ + cj],
                       make_float2(e10, e11));
            }
            *(__half2*)&Qs[(w * 16 + g) * 72 + nt * 8 + 2 * t]     = __floats2half2_rn(e00, e01);
            *(__half2*)&Qs[(w * 16 + g + 8) * 72 + nt * 8 + 2 * t] = __floats2half2_rn(e10, e11);
        }
        __syncwarp();

        // GEMM2: ctx += P V
#pragma unroll
        for (int ks = 0; ks < 4; ks++) {
            unsigned pa[4];
            ldsm4(pa, qpA + ks * 32);
#pragma unroll
            for (int ntp = 0; ntp < 4; ntp++) {
                unsigned bv[4];
                ldsm4t(bv, Vbp + ks * 2304 + ntp * 32 + offA);
                mma_f16(ctx[2 * ntp],     pa, bv);
                mma_f16(ctx[2 * ntp + 1], pa, bv + 2);
            }
        }

        if (ct < ctmax) {
            if (ct + 2 <= ctmax) { CP_WAIT1(); } else { CP_WAIT0(); }
            __syncthreads();
        }
    }

    // Store ctx as fp16
    const int b = bh >> 3, h = bh & 7;
#pragma unroll
    for (int nt = 0; nt < 8; nt++) {
        const int d = nt * 8 + 2 * t;
        *(__half2*)&g_ctxh[((size_t)(b * SS_ + gi0)) * DD + h * 64 + d] =
            __floats2half2_rn(ctx[nt][0], ctx[nt][1]);
        *(__half2*)&g_ctxh[((size_t)(b * SS_ + gi1)) * DD + h * 64 + d] =
            __floats2half2_rn(ctx[nt][2], ctx[nt][3]);
    }
}

// ---------------------------------------------------------------------------
extern "C" void kernel_launch(void* const* d_in, const int* in_sizes, int n_in,
                              void* d_out, int out_size) {
    const float* q  = (const float*)d_in[2];
    const float* k  = (const float*)d_in[0];
    const float* v  = (const float*)d_in[1];
    const float* Wq = (const float*)d_in[4];
    const float* bq = (const float*)d_in[5];
    const float* Wk = (const float*)d_in[6];
    const float* bk = (const float*)d_in[7];
    const float* Wv = (const float*)d_in[8];
    const float* bv = (const float*)d_in[9];
    const float* Wo = (const float*)d_in[10];
    const float* bo = (const float*)d_in[11];

    float* out = (float*)d_out;
    const size_t BSD = (size_t)BB * SS_ * DD;
    const size_t ATT = (size_t)BH * SS_ * SS_;

    float* out_main = nullptr;
    float* attn_out = nullptr;
    if ((size_t)out_size >= BSD + ATT) {
        out_main = out;
        attn_out = out + BSD;
    } else if ((size_t)out_size >= ATT) {
        attn_out = out;
    } else {
        out_main = out;
    }

    void *pxq, *pxk, *pxv, *pwq, *pwk, *pwv, *pwo;
    void *pq, *pk, *pv, *pctx;
    cudaGetSymbolAddress(&pxq, g_xq);
    cudaGetSymbolAddress(&pxk, g_xk);
    cudaGetSymbolAddress(&pxv, g_xv);
    cudaGetSymbolAddress(&pwq, g_wq);
    cudaGetSymbolAddress(&pwk, g_wk);
    cudaGetSymbolAddress(&pwv, g_wv);
    cudaGetSymbolAddress(&pwo, g_wo);
    cudaGetSymbolAddress(&pq, g_qh);
    cudaGetSymbolAddress(&pk, g_kh);
    cudaGetSymbolAddress(&pv, g_vh);
    cudaGetSymbolAddress(&pctx, g_ctxh);

    cudaFuncSetAttribute(attn_fused,
                         cudaFuncAttributeMaxDynamicSharedMemorySize, 73728);
    cudaFuncSetAttribute(gemm_f16k<0>,
                         cudaFuncAttributeMaxDynamicSharedMemorySize, 37888);
    cudaFuncSetAttribute(gemm_f16k<1>,
                         cudaFuncAttributeMaxDynamicSharedMemorySize, 37888);

    // Fused converts: 2 launches
    f32to16_act<<<3 * 4096, 256>>>(q, k, v,
                                   (__half*)pxq, (__half*)pxk, (__half*)pxv);
    f32to16_wts<<<4 * 256, 256>>>(Wq, Wk, Wv, Wo,
                                  (__half*)pwq, (__half*)pwk,
                                  (__half*)pwv, (__half*)pwo);

    // Batched QKV projection: one launch, gridDim.z = 3
    GemmBatch qkv;
    qkv.X[0] = (const __half*)pxq; qkv.W[0] = (const __half*)pwq;
    qkv.bias[0] = bq; qkv.Y[0] = (float*)pq;
    qkv.X[1] = (const __half*)pxk; qkv.W[1] = (const __half*)pwk;
    qkv.bias[1] = bk; qkv.Y[1] = (float*)pk;
    qkv.X[2] = (const __half*)pxv; qkv.W[2] = (const __half*)pwv;
    qkv.bias[2] = bv; qkv.Y[2] = (float*)pv;
    gemm_f16k<1><<<dim3(4, 64, 3), 256, 37888>>>(qkv);

    // Fused rowsum + zerofill + attention
    attn_fused<<<dim3(32, BH), 256, 73728>>>(attn_out, attn_out != nullptr);

    if (out_main) {
        GemmBatch ob;
        ob.X[0] = (const __half*)pctx; ob.W[0] = (const __half*)pwo;
        ob.bias[0] = bo; ob.Y[0] = out_main;
        ob.X[1] = ob.X[0]; ob.W[1] = ob.W[0]; ob.bias[1] = ob.bias[0]; ob.Y[1] = ob.Y[0];
        ob.X[2] = ob.X[0]; ob.W[2] = ob.W[0]; ob.bias[2] = ob.bias[0]; ob.Y[2] = ob.Y[0];
        gemm_f16k<0><<<dim3(4, 64, 1), 256, 37888>>>(ob);
    }
}